// round 9
// baseline (speedup 1.0000x reference)
#include <cuda_runtime.h>

#define N_NODES 10000
#define N_EDGES 320000
#define D_IN    128
#define D_HID   64
#define D_OUT   16
#define NH      (N_NODES * D_HID)
#define AAM     5
#define TPB         512
#define BLK_PER_SM  3
#define GRID_BLOCKS 444              // 148 SMs x 3 blocks guaranteed resident
#define NWARPS      (GRID_BLOCKS * (TPB / 32))   // 7104
#define NTHREADS    (GRID_BLOCKS * TPB)
#define NODE_COST   48
#define COST_TOTAL  (N_EDGES + NODE_COST * N_NODES)

typedef unsigned long long ull;

// ---------------- device scratch ----------------
__device__ float  g_b[NH];
__device__ float  g_u[NH];
__device__ float  g_wbuf[2][NH];          // ping-pong SPMM input
__device__ float  g_F[AAM][NH];
__device__ float  g_G[AAM][NH];
__device__ float  g_ThT[D_HID * D_HID];   // ThT[k*64+c] = Theta[c][k]
__device__ int    g_rowptr[N_NODES + 1];
__device__ int    g_cur[N_NODES];
__device__ int2   g_edge[N_EDGES];
__device__ int    g_wstart[NWARPS + 1];
__device__ double g_GGbuf[2][15];
__device__ double g_GGrow[2][5];
__device__ unsigned          g_bar_cnt;
__device__ volatile unsigned g_bar_gen;

union SmemU {
    struct { float M[64][128]; float fct[64]; } th;            // 33 KB (setup)
    struct {
        ull A[32][32];            // ThA[m][l] = (Th[2l][2m],   Th[2l][2m+1])
        ull B[32][32];            // ThB[m][l] = (Th[2l+1][2m], Th[2l+1][2m+1])
        ull s[TPB / 32][32];      // per-warp staged s vector
    } mix;                        // 20 KB (spmm phases)
    int part[TPB];
};

// ---------------- f32x2 helpers ----------------
__device__ __forceinline__ void fma2(ull& d, ull a, ull b) {
    asm("fma.rn.f32x2 %0, %1, %2, %0;" : "+l"(d) : "l"(a), "l"(b));
}
__device__ __forceinline__ ull pack2(float2 v) {
    ull r; asm("mov.b64 %0, {%1, %2};" : "=l"(r) : "f"(v.x), "f"(v.y)); return r;
}
__device__ __forceinline__ float2 unpack2(ull v) {
    float2 r; asm("mov.b64 {%0, %1}, %2;" : "=f"(r.x), "=f"(r.y) : "l"(v)); return r;
}

// ---------------- software grid barrier ----------------
__device__ __forceinline__ void gbar() {
    __syncthreads();
    if (threadIdx.x == 0) {
        __threadfence();
        unsigned gen = g_bar_gen;
        if (atomicAdd(&g_bar_cnt, 1u) == GRID_BLOCKS - 1u) {
            g_bar_cnt = 0u;
            __threadfence();
            g_bar_gen = gen + 1u;
        } else {
            while (g_bar_gen == gen) { __nanosleep(64); }
        }
        __threadfence();
    }
    __syncthreads();
}

// ---------------- Cayley: Theta = (I+Om)^-1 (I-Om) ----------------
__device__ void theta_phase(const float* __restrict__ B, SmemU* su) {
    int tid = threadIdx.x;
    for (int idx = tid; idx < 64 * 64; idx += TPB) {
        int i = idx >> 6, j = idx & 63;
        float om = 0.5f * (B[i * 64 + j] - B[j * 64 + i]);
        float e  = (i == j) ? 1.f : 0.f;
        su->th.M[i][j]      = e + om;
        su->th.M[i][64 + j] = e - om;
    }
    __syncthreads();
    for (int k = 0; k < 64; k++) {
        float inv = 1.f / su->th.M[k][k];
        __syncthreads();
        for (int j = tid; j < 128; j += TPB) su->th.M[k][j] *= inv;
        __syncthreads();
        for (int r = tid; r < 64; r += TPB) su->th.fct[r] = su->th.M[r][k];
        __syncthreads();
        for (int idx = tid; idx < 64 * 128; idx += TPB) {
            int r = idx >> 7, j = idx & 127;
            if (r != k) su->th.M[r][j] -= su->th.fct[r] * su->th.M[k][j];
        }
        __syncthreads();
    }
    for (int idx = tid; idx < 64 * 64; idx += TPB) {
        int k = idx >> 6, c = idx & 63;
        g_ThT[idx] = su->th.M[c][64 + k];
    }
}

// ---------------- encoder + u0/w0 ----------------
__device__ void encode_phase(const float* __restrict__ x, const float* __restrict__ W,
                             const float* __restrict__ bias) {
    int warp = threadIdx.x >> 5, cp = threadIdx.x & 31;
    int g = blockIdx.x * (TPB / 32) + warp;
    const float2* __restrict__ W2 = (const float2*)W;
    float2 bsv = ((const float2*)bias)[cp];
    for (int node = g; node < N_NODES; node += NWARPS) {
        const float* __restrict__ xr = x + node * D_IN;
        float2 acc = bsv;
#pragma unroll 16
        for (int k = 0; k < D_IN; k++) {
            float  xk = xr[k];
            float2 w2 = W2[k * 32 + cp];
            acc.x = fmaf(xk, w2.x, acc.x);
            acc.y = fmaf(xk, w2.y, acc.y);
        }
        int row = node * 32 + cp;
        ((float2*)g_b)[row] = acc;
        ((float2*)g_u)[row] = acc;
        ((float2*)g_wbuf[0])[row] = make_float2(2.f * fmaxf(acc.x, 0.f),
                                                2.f * fmaxf(acc.y, 0.f));
    }
}

// ---------------- single-node gather, unroll 4 ----------------
__device__ __forceinline__ float2 gather(const int2* __restrict__ eg,
                                         const float2* __restrict__ wv,
                                         int e, int end, int lane) {
    float2 a0 = {0.f, 0.f}, a1 = {0.f, 0.f};
    for (; e + 4 <= end; e += 4) {
        int2 d0 = eg[e], d1 = eg[e + 1], d2 = eg[e + 2], d3 = eg[e + 3];
        float2 v0 = wv[d0.x * 32 + lane], v1 = wv[d1.x * 32 + lane];
        float2 v2 = wv[d2.x * 32 + lane], v3 = wv[d3.x * 32 + lane];
        float w0 = __int_as_float(d0.y), w1 = __int_as_float(d1.y);
        float w2 = __int_as_float(d2.y), w3 = __int_as_float(d3.y);
        a0.x = fmaf(w0, v0.x, a0.x); a0.y = fmaf(w0, v0.y, a0.y);
        a1.x = fmaf(w1, v1.x, a1.x); a1.y = fmaf(w1, v1.y, a1.y);
        a0.x = fmaf(w2, v2.x, a0.x); a0.y = fmaf(w2, v2.y, a0.y);
        a1.x = fmaf(w3, v3.x, a1.x); a1.y = fmaf(w3, v3.y, a1.y);
    }
    for (; e < end; ++e) {
        int2 d = eg[e];
        float2 v = wv[d.x * 32 + lane];
        float ww = __int_as_float(d.y);
        a0.x = fmaf(ww, v.x, a0.x); a0.y = fmaf(ww, v.y, a0.y);
    }
    return make_float2(a0.x + a1.x, a0.y + a1.y);
}

// ---------------- fused SPMM + shuffle-free mix + G + Gram partials ----------------
__device__ void spmm_phase(int slot, int npairs, double* target, int wr_next,
                           const float* __restrict__ wsrc, float* __restrict__ wdst,
                           SmemU* su, double (*red)[5]) {
    int warp = threadIdx.x >> 5, lane = threadIdx.x & 31;
    int w = blockIdx.x * (TPB / 32) + warp;
    const int2*   __restrict__ eg = g_edge;
    const float2* __restrict__ wv = (const float2*)wsrc;
    float p[5];
#pragma unroll
    for (int j = 0; j < 5; j++) p[j] = 0.f;

    int n = g_wstart[w], ne = g_wstart[w + 1];

    for (; n < ne; ++n) {
        int r0 = g_rowptr[n], r1 = g_rowptr[n + 1];
        float2 acc = gather(eg, wv, r0, r1, lane);

        __syncwarp();
        su->mix.s[warp][lane] = pack2(acc);
        __syncwarp();

        ull PA = 0ull, QA = 0ull;
#pragma unroll
        for (int m = 0; m < 32; ++m) {
            ull sp = su->mix.s[warp][m];   // broadcast LDS.64
            fma2(PA, su->mix.A[m][lane], sp);
            fma2(QA, su->mix.B[m][lane], sp);
        }
        float2 pA = unpack2(PA), qA = unpack2(QA);
        float2 mix = make_float2(pA.x + pA.y, qA.x + qA.y);

        // epilogue
        int row = n * 32 + lane;
        float2 bb = ((const float2*)g_b)[row];
        float2 uu = ((const float2*)g_u)[row];
        float2 val = make_float2(bb.x + 0.5f * mix.x, bb.y + 0.5f * mix.y);
        ((float2*)g_F[slot])[row] = val;
        float2 gn = make_float2(val.x - uu.x, val.y - uu.y);
        ((float2*)g_G[slot])[row] = gn;
        if (wr_next) {
            ((float2*)g_u)[row] = val;
            ((float2*)wdst)[row] = make_float2(2.f * fmaxf(val.x, 0.f) - val.x + bb.x,
                                               2.f * fmaxf(val.y, 0.f) - val.y + bb.y);
        }
        for (int j = 0; j < npairs; ++j) {
            float2 gj = (j == slot) ? gn : ((const float2*)g_G[j])[row];
            p[j] = fmaf(gn.x, gj.x, fmaf(gn.y, gj.y, p[j]));
        }
    }

#pragma unroll
    for (int j = 0; j < 5; ++j)
        for (int off = 16; off > 0; off >>= 1)
            p[j] += __shfl_down_sync(0xffffffffu, p[j], off);
    __syncthreads();
    if (lane == 0)
        for (int j = 0; j < 5; ++j) red[warp][j] = (double)p[j];
    __syncthreads();
    if (threadIdx.x < npairs) {
        int j = threadIdx.x;
        double s = 0.0;
        for (int ww = 0; ww < TPB / 32; ww++) s += red[ww][j];
        atomicAdd(&target[j], s);
    }
}

// ---------------- combine(k): Gram merge + 5x5 solve + u_new (+ fused decode at k=4) ----------------
__device__ void combine_phase(int k, float* sa, const float* __restrict__ decW,
                              float* __restrict__ out) {
    if (threadIdx.x == 0) {
        double M[5][5];
        const double* base = g_GGbuf[k & 1];
        int c = 0;
        for (int i = 0; i < 5; i++)
            for (int j = 0; j <= i; j++) { M[i][j] = base[c]; M[j][i] = base[c]; c++; }
        if (k > 0) {
            int idx = k - 1;
            const double* row = g_GGrow[(k - 1) & 1];
            for (int j = 0; j < 5; j++) { M[idx][j] = row[j]; M[j][idx] = row[j]; }
        }
        if (blockIdx.x == 0 && k < AAM - 1) {
            c = 0;
            for (int i = 0; i < 5; i++)
                for (int j = 0; j <= i; j++) g_GGbuf[(k + 1) & 1][c++] = M[i][j];
            for (int j = 0; j < 5; j++) g_GGrow[k & 1][j] = 0.0;
        }
        float A[5][6];
        for (int i = 0; i < 5; i++) {
            for (int j = 0; j < 5; j++) A[i][j] = (float)M[i][j];
            A[i][i] += 1e-4f;
            A[i][5] = 1.f;
        }
        for (int kk = 0; kk < 5; kk++) {
            int piv = kk; float mx = fabsf(A[kk][kk]);
            for (int r = kk + 1; r < 5; r++)
                if (fabsf(A[r][kk]) > mx) { mx = fabsf(A[r][kk]); piv = r; }
            if (piv != kk)
                for (int j = 0; j < 6; j++) { float t = A[kk][j]; A[kk][j] = A[piv][j]; A[piv][j] = t; }
            float inv = 1.f / A[kk][kk];
            for (int r = kk + 1; r < 5; r++) {
                float f = A[r][kk] * inv;
                for (int j = kk; j < 6; j++) A[r][j] -= f * A[kk][j];
            }
        }
        float a[5];
        for (int kk = 4; kk >= 0; kk--) {
            float s = A[kk][5];
            for (int j = kk + 1; j < 5; j++) s -= A[kk][j] * a[j];
            a[kk] = s / A[kk][kk];
        }
        float sum = a[0] + a[1] + a[2] + a[3] + a[4];
        for (int j = 0; j < 5; j++) sa[j] = a[j] / sum;
    }
    __syncthreads();
    float a0 = sa[0], a1 = sa[1], a2 = sa[2], a3 = sa[3], a4 = sa[4];

    int warp = threadIdx.x >> 5, lane = threadIdx.x & 31;
    int g = blockIdx.x * (TPB / 32) + warp;
    const float2* F0 = (const float2*)g_F[0];
    const float2* F1 = (const float2*)g_F[1];
    const float2* F2 = (const float2*)g_F[2];
    const float2* F3 = (const float2*)g_F[3];
    const float2* F4 = (const float2*)g_F[4];
    for (int node = g; node < N_NODES; node += NWARPS) {
        int idx = node * 32 + lane;
        float2 f0 = F0[idx], f1 = F1[idx], f2 = F2[idx], f3 = F3[idx], f4 = F4[idx];
        float2 un;
        un.x = a0 * f0.x + a1 * f1.x + a2 * f2.x + a3 * f3.x + a4 * f4.x;
        un.y = a0 * f0.y + a1 * f1.y + a2 * f2.y + a3 * f3.y + a4 * f4.y;
        if (k < AAM - 1) {
            ((float2*)g_u)[idx] = un;
            float2 bb = ((const float2*)g_b)[idx];
            ((float2*)g_wbuf[0])[idx] =
                make_float2(2.f * fmaxf(un.x, 0.f) - un.x + bb.x,
                            2.f * fmaxf(un.y, 0.f) - un.y + bb.y);
        } else {
            float rx = fmaxf(un.x, 0.f), ry = fmaxf(un.y, 0.f);
            int o = lane & 15, half = lane >> 4;
            float acc = 0.f;
#pragma unroll
            for (int i = 0; i < 16; i++) {
                int m = half * 16 + i;
                float sx = __shfl_sync(0xffffffffu, rx, m);
                float sy = __shfl_sync(0xffffffffu, ry, m);
                acc = fmaf(sx, decW[(2 * m) * 16 + o], acc);
                acc = fmaf(sy, decW[(2 * m + 1) * 16 + o], acc);
            }
            acc += __shfl_down_sync(0xffffffffu, acc, 16);
            if (half == 0) out[node * 16 + o] = acc;
        }
    }
}

// ---------------- the single persistent kernel ----------------
__global__ void __launch_bounds__(TPB, BLK_PER_SM) k_mega(
    const float* __restrict__ x, const int* __restrict__ ei,
    const float* __restrict__ ew, const float* __restrict__ encW,
    const float* __restrict__ encb, const float* __restrict__ cayB,
    const float* __restrict__ decW, float* __restrict__ out)
{
    __shared__ SmemU su;
    __shared__ double red[TPB / 32][5];
    __shared__ float sa[5];

    const int* src = ei;
    const int* dst = ei + N_EDGES;
    int gtid = blockIdx.x * TPB + threadIdx.x;

    // A: zero counters + Gram buf
    for (int i = gtid; i < N_NODES; i += NTHREADS) g_cur[i] = 0;
    if (gtid < 15) g_GGbuf[0][gtid] = 0.0;
    gbar();

    // B: degree histogram || encoder + u0/w0
    for (int e = gtid; e < N_EDGES; e += NTHREADS) atomicAdd(&g_cur[dst[e]], 1);
    encode_phase(x, encW, encb);
    gbar();

    // C: prefix scan (block 0) || Cayley theta (block 1)
    if (blockIdx.x == 0) {
        int t = threadIdx.x;
        const int CH = (N_NODES + TPB - 1) / TPB;   // 20
        int beg = t * CH, end = beg + CH; if (end > N_NODES) end = N_NODES;
        int s = 0;
        for (int i = beg; i < end; i++) s += g_cur[i];
        su.part[t] = s;
        __syncthreads();
        for (int d = 1; d < TPB; d <<= 1) {
            int v = (t >= d) ? su.part[t - d] : 0;
            __syncthreads();
            su.part[t] += v;
            __syncthreads();
        }
        int off = (t > 0) ? su.part[t - 1] : 0;
        for (int i = beg; i < end; i++) {
            int c = g_cur[i];
            g_rowptr[i] = off;
            g_cur[i]    = off;
            off += c;
        }
        if (t == 0) g_rowptr[N_NODES] = N_EDGES;
    } else if (blockIdx.x == 1) {
        theta_phase(cayB, &su);
    }
    gbar();

    // D: CSR scatter || balanced warp partition || stage dual Theta layouts
    for (int e = gtid; e < N_EDGES; e += NTHREADS) {
        int d = dst[e];
        int p = atomicAdd(&g_cur[d], 1);
        g_edge[p] = make_int2(src[e], __float_as_int(ew[e]));
    }
    if (gtid <= NWARPS) {
        if (gtid == NWARPS) {
            g_wstart[NWARPS] = N_NODES;
        } else {
            long long target = (long long)gtid * COST_TOTAL / NWARPS;
            int lo = 0, hi = N_NODES;
            while (lo < hi) {
                int mid = (lo + hi) >> 1;
                long long c = (long long)g_rowptr[mid] + (long long)NODE_COST * mid;
                if (c < target) lo = mid + 1; else hi = mid;
            }
            g_wstart[gtid] = lo;
        }
    }
    for (int i = threadIdx.x; i < 1024; i += TPB) {
        int m = i >> 5, l = i & 31;
        float a0 = g_ThT[(2 * m) * 64 + 2 * l];
        float a1 = g_ThT[(2 * m + 1) * 64 + 2 * l];
        float b0 = g_ThT[(2 * m) * 64 + 2 * l + 1];
        float b1 = g_ThT[(2 * m + 1) * 64 + 2 * l + 1];
        su.mix.A[m][l] = pack2(make_float2(a0, a1));
        su.mix.B[m][l] = pack2(make_float2(b0, b1));
    }
    gbar();

    // history: 5 PR sweeps (w ping-pong), Gram lower-tri into GGbuf[0]
    for (int i = 0; i < AAM; i++) {
        spmm_phase(i, i + 1, &g_GGbuf[0][i * (i + 1) / 2], (i < AAM - 1) ? 1 : 0,
                   g_wbuf[i & 1], g_wbuf[(i + 1) & 1], &su, red);
        gbar();
    }

    // Anderson: combine -> spmm (last g() dead); final combine fuses decode
    for (int k = 0; k < AAM; k++) {
        combine_phase(k, sa, decW, out);
        if (k < AAM - 1) {
            gbar();
            spmm_phase(k, 5, g_GGrow[k & 1], 0, g_wbuf[0], 0, &su, red);
            gbar();
        }
    }
}

// ---------------- launch: ONE kernel ----------------
extern "C" void kernel_launch(void* const* d_in, const int* in_sizes, int n_in,
                              void* d_out, int out_size) {
    const float* x    = (const float*)d_in[0];
    const int*   ei   = (const int*)  d_in[1];
    const float* ew   = (const float*)d_in[2];
    const float* encW = (const float*)d_in[3];
    const float* encb = (const float*)d_in[4];
    const float* cayB = (const float*)d_in[5];
    const float* decW = (const float*)d_in[6];
    float* out = (float*)d_out;

    k_mega<<<GRID_BLOCKS, TPB>>>(x, ei, ew, encW, encb, cayB, decW, out);
}

// round 10
// speedup vs baseline: 1.0687x; 1.0687x over previous
#include <cuda_runtime.h>

#define N_NODES 10000
#define N_EDGES 320000
#define D_IN    128
#define D_HID   64
#define D_OUT   16
#define NH      (N_NODES * D_HID)
#define AAM     5
#define TPB         1024
#define BLK_PER_SM  1
#define GRID_BLOCKS 148              // 1 block per SM
#define WPB         (TPB / 32)       // 32 warps/block
#define NWARPS      (GRID_BLOCKS * WPB)          // 4736
#define NTHREADS    (GRID_BLOCKS * TPB)
#define NODE_COST   48
#define COST_TOTAL  (N_EDGES + NODE_COST * N_NODES)

typedef unsigned long long ull;

// ---------------- device scratch ----------------
__device__ float  g_b[NH];
__device__ float  g_u[NH];                // written only by Anderson combines
__device__ float  g_wbuf[2][NH];          // ping-pong SPMM input
__device__ float  g_F[AAM][NH];
__device__ float  g_G[AAM][NH];
__device__ float  g_ThT[D_HID * D_HID];   // ThT[k*64+c] = Theta[c][k]
__device__ int    g_rowptr[N_NODES + 1];
__device__ int    g_cur[N_NODES];
__device__ int2   g_edge[N_EDGES];
__device__ int    g_wstart[NWARPS + 1];
__device__ double g_GGbuf[2][15];
__device__ double g_GGrow[2][5];
__device__ unsigned          g_bar_cnt;
__device__ volatile unsigned g_bar_gen;

union SmemU {
    struct { float M[64][128]; float fct[64]; } th;            // 33 KB (setup)
    struct {
        ull A[32][32];            // ThA[m][l] = (Th[2l][2m],   Th[2l][2m+1])
        ull B[32][32];            // ThB[m][l] = (Th[2l+1][2m], Th[2l+1][2m+1])
        ull s[WPB][2][32];        // per-warp staged s vectors (A, B)
    } mix;                        // 32 KB (spmm phases)
    int part[TPB];
};

// ---------------- f32x2 helpers ----------------
__device__ __forceinline__ void fma2(ull& d, ull a, ull b) {
    asm("fma.rn.f32x2 %0, %1, %2, %0;" : "+l"(d) : "l"(a), "l"(b));
}
__device__ __forceinline__ ull pack2(float2 v) {
    ull r; asm("mov.b64 %0, {%1, %2};" : "=l"(r) : "f"(v.x), "f"(v.y)); return r;
}
__device__ __forceinline__ float2 unpack2(ull v) {
    float2 r; asm("mov.b64 {%0, %1}, %2;" : "=f"(r.x), "=f"(r.y) : "l"(v)); return r;
}

// ---------------- software grid barrier (148 blocks, all resident) ----------------
__device__ __forceinline__ void gbar() {
    __syncthreads();
    if (threadIdx.x == 0) {
        __threadfence();
        unsigned gen = g_bar_gen;
        if (atomicAdd(&g_bar_cnt, 1u) == GRID_BLOCKS - 1u) {
            g_bar_cnt = 0u;
            __threadfence();
            g_bar_gen = gen + 1u;
        } else {
            while (g_bar_gen == gen) { __nanosleep(32); }
        }
        __threadfence();
    }
    __syncthreads();
}

// ---------------- Cayley: Theta = (I+Om)^-1 (I-Om) ----------------
__device__ void theta_phase(const float* __restrict__ B, SmemU* su) {
    int tid = threadIdx.x;
    for (int idx = tid; idx < 64 * 64; idx += TPB) {
        int i = idx >> 6, j = idx & 63;
        float om = 0.5f * (B[i * 64 + j] - B[j * 64 + i]);
        float e  = (i == j) ? 1.f : 0.f;
        su->th.M[i][j]      = e + om;
        su->th.M[i][64 + j] = e - om;
    }
    __syncthreads();
    for (int k = 0; k < 64; k++) {
        float inv = 1.f / su->th.M[k][k];
        __syncthreads();
        for (int j = tid; j < 128; j += TPB) su->th.M[k][j] *= inv;
        __syncthreads();
        for (int r = tid; r < 64; r += TPB) su->th.fct[r] = su->th.M[r][k];
        __syncthreads();
        for (int idx = tid; idx < 64 * 128; idx += TPB) {
            int r = idx >> 7, j = idx & 127;
            if (r != k) su->th.M[r][j] -= su->th.fct[r] * su->th.M[k][j];
        }
        __syncthreads();
    }
    for (int idx = tid; idx < 64 * 64; idx += TPB) {
        int k = idx >> 6, c = idx & 63;
        g_ThT[idx] = su->th.M[c][64 + k];
    }
}

// ---------------- encoder + b/w0 ----------------
__device__ void encode_phase(const float* __restrict__ x, const float* __restrict__ W,
                             const float* __restrict__ bias) {
    int warp = threadIdx.x >> 5, cp = threadIdx.x & 31;
    int g = blockIdx.x * WPB + warp;
    const float2* __restrict__ W2 = (const float2*)W;
    float2 bsv = ((const float2*)bias)[cp];
    for (int node = g; node < N_NODES; node += NWARPS) {
        const float* __restrict__ xr = x + node * D_IN;
        float2 acc = bsv;
#pragma unroll 16
        for (int k = 0; k < D_IN; k++) {
            float  xk = xr[k];
            float2 w2 = W2[k * 32 + cp];
            acc.x = fmaf(xk, w2.x, acc.x);
            acc.y = fmaf(xk, w2.y, acc.y);
        }
        int row = node * 32 + cp;
        ((float2*)g_b)[row] = acc;
        ((float2*)g_wbuf[0])[row] = make_float2(2.f * fmaxf(acc.x, 0.f),
                                                2.f * fmaxf(acc.y, 0.f));
    }
}

// ---------------- interleaved dual-node gather ----------------
__device__ __forceinline__ void gather2(const int2* __restrict__ eg,
                                        const float2* __restrict__ wv,
                                        int eA, int endA, int eB, int endB,
                                        int lane, float2& outA, float2& outB) {
    float2 aA0 = {0.f, 0.f}, aA1 = {0.f, 0.f};
    float2 aB0 = {0.f, 0.f}, aB1 = {0.f, 0.f};
    while (eA + 4 <= endA && eB + 4 <= endB) {
        int2 dA0 = eg[eA], dA1 = eg[eA + 1], dA2 = eg[eA + 2], dA3 = eg[eA + 3];
        int2 dB0 = eg[eB], dB1 = eg[eB + 1], dB2 = eg[eB + 2], dB3 = eg[eB + 3];
        float2 vA0 = wv[dA0.x * 32 + lane], vA1 = wv[dA1.x * 32 + lane];
        float2 vA2 = wv[dA2.x * 32 + lane], vA3 = wv[dA3.x * 32 + lane];
        float2 vB0 = wv[dB0.x * 32 + lane], vB1 = wv[dB1.x * 32 + lane];
        float2 vB2 = wv[dB2.x * 32 + lane], vB3 = wv[dB3.x * 32 + lane];
        float wA0 = __int_as_float(dA0.y), wA1 = __int_as_float(dA1.y);
        float wA2 = __int_as_float(dA2.y), wA3 = __int_as_float(dA3.y);
        float wB0 = __int_as_float(dB0.y), wB1 = __int_as_float(dB1.y);
        float wB2 = __int_as_float(dB2.y), wB3 = __int_as_float(dB3.y);
        aA0.x = fmaf(wA0, vA0.x, aA0.x); aA0.y = fmaf(wA0, vA0.y, aA0.y);
        aA1.x = fmaf(wA1, vA1.x, aA1.x); aA1.y = fmaf(wA1, vA1.y, aA1.y);
        aA0.x = fmaf(wA2, vA2.x, aA0.x); aA0.y = fmaf(wA2, vA2.y, aA0.y);
        aA1.x = fmaf(wA3, vA3.x, aA1.x); aA1.y = fmaf(wA3, vA3.y, aA1.y);
        aB0.x = fmaf(wB0, vB0.x, aB0.x); aB0.y = fmaf(wB0, vB0.y, aB0.y);
        aB1.x = fmaf(wB1, vB1.x, aB1.x); aB1.y = fmaf(wB1, vB1.y, aB1.y);
        aB0.x = fmaf(wB2, vB2.x, aB0.x); aB0.y = fmaf(wB2, vB2.y, aB0.y);
        aB1.x = fmaf(wB3, vB3.x, aB1.x); aB1.y = fmaf(wB3, vB3.y, aB1.y);
        eA += 4; eB += 4;
    }
    for (; eA + 4 <= endA; eA += 4) {
        int2 d0 = eg[eA], d1 = eg[eA + 1], d2 = eg[eA + 2], d3 = eg[eA + 3];
        float2 v0 = wv[d0.x * 32 + lane], v1 = wv[d1.x * 32 + lane];
        float2 v2 = wv[d2.x * 32 + lane], v3 = wv[d3.x * 32 + lane];
        float w0 = __int_as_float(d0.y), w1 = __int_as_float(d1.y);
        float w2 = __int_as_float(d2.y), w3 = __int_as_float(d3.y);
        aA0.x = fmaf(w0, v0.x, aA0.x); aA0.y = fmaf(w0, v0.y, aA0.y);
        aA1.x = fmaf(w1, v1.x, aA1.x); aA1.y = fmaf(w1, v1.y, aA1.y);
        aA0.x = fmaf(w2, v2.x, aA0.x); aA0.y = fmaf(w2, v2.y, aA0.y);
        aA1.x = fmaf(w3, v3.x, aA1.x); aA1.y = fmaf(w3, v3.y, aA1.y);
    }
    for (; eA < endA; ++eA) {
        int2 d = eg[eA];
        float2 v = wv[d.x * 32 + lane];
        float ww = __int_as_float(d.y);
        aA0.x = fmaf(ww, v.x, aA0.x); aA0.y = fmaf(ww, v.y, aA0.y);
    }
    for (; eB + 4 <= endB; eB += 4) {
        int2 d0 = eg[eB], d1 = eg[eB + 1], d2 = eg[eB + 2], d3 = eg[eB + 3];
        float2 v0 = wv[d0.x * 32 + lane], v1 = wv[d1.x * 32 + lane];
        float2 v2 = wv[d2.x * 32 + lane], v3 = wv[d3.x * 32 + lane];
        float w0 = __int_as_float(d0.y), w1 = __int_as_float(d1.y);
        float w2 = __int_as_float(d2.y), w3 = __int_as_float(d3.y);
        aB0.x = fmaf(w0, v0.x, aB0.x); aB0.y = fmaf(w0, v0.y, aB0.y);
        aB1.x = fmaf(w1, v1.x, aB1.x); aB1.y = fmaf(w1, v1.y, aB1.y);
        aB0.x = fmaf(w2, v2.x, aB0.x); aB0.y = fmaf(w2, v2.y, aB0.y);
        aB1.x = fmaf(w3, v3.x, aB1.x); aB1.y = fmaf(w3, v3.y, aB1.y);
    }
    for (; eB < endB; ++eB) {
        int2 d = eg[eB];
        float2 v = wv[d.x * 32 + lane];
        float ww = __int_as_float(d.y);
        aB0.x = fmaf(ww, v.x, aB0.x); aB0.y = fmaf(ww, v.y, aB0.y);
    }
    outA = make_float2(aA0.x + aA1.x, aA0.y + aA1.y);
    outB = make_float2(aB0.x + aB1.x, aB0.y + aB1.y);
}

// ---------------- per-node epilogue ----------------
__device__ __forceinline__ void epilogue(int node, int lane, float2 mix, int slot,
                                         int npairs, int wr_next,
                                         const float* __restrict__ usrc,
                                         float* __restrict__ wdst, float* p) {
    int row = node * 32 + lane;
    float2 bb = ((const float2*)g_b)[row];
    float2 uu = ((const float2*)usrc)[row];
    float2 val = make_float2(bb.x + 0.5f * mix.x, bb.y + 0.5f * mix.y);
    ((float2*)g_F[slot])[row] = val;
    float2 gn = make_float2(val.x - uu.x, val.y - uu.y);
    ((float2*)g_G[slot])[row] = gn;
    if (wr_next) {
        ((float2*)wdst)[row] = make_float2(2.f * fmaxf(val.x, 0.f) - val.x + bb.x,
                                           2.f * fmaxf(val.y, 0.f) - val.y + bb.y);
    }
    for (int j = 0; j < npairs; ++j) {
        float2 gj = (j == slot) ? gn : ((const float2*)g_G[j])[row];
        p[j] = fmaf(gn.x, gj.x, fmaf(gn.y, gj.y, p[j]));
    }
}

// ---------------- fused SPMM + shuffle-free mix + G + Gram partials ----------------
__device__ void spmm_phase(int slot, int npairs, double* target, int wr_next,
                           const float* __restrict__ wsrc,
                           const float* __restrict__ usrc,
                           float* __restrict__ wdst,
                           SmemU* su, double (*red)[5]) {
    int warp = threadIdx.x >> 5, lane = threadIdx.x & 31;
    int w = blockIdx.x * WPB + warp;
    const int2*   __restrict__ eg = g_edge;
    const float2* __restrict__ wv = (const float2*)wsrc;
    float p[5];
#pragma unroll
    for (int j = 0; j < 5; j++) p[j] = 0.f;

    int n = g_wstart[w], ne = g_wstart[w + 1];

    for (; n + 1 < ne; n += 2) {
        int r0 = g_rowptr[n], r1 = g_rowptr[n + 1], r2 = g_rowptr[n + 2];
        float2 accA, accB;
        gather2(eg, wv, r0, r1, r1, r2, lane, accA, accB);

        __syncwarp();
        su->mix.s[warp][0][lane] = pack2(accA);
        su->mix.s[warp][1][lane] = pack2(accB);
        __syncwarp();

        ull PA = 0ull, QA = 0ull, PB = 0ull, QB = 0ull;
#pragma unroll
        for (int m = 0; m < 32; ++m) {
            ull spA = su->mix.s[warp][0][m];   // broadcast LDS.64
            ull spB = su->mix.s[warp][1][m];
            ull TA  = su->mix.A[m][lane];
            ull TB  = su->mix.B[m][lane];
            fma2(PA, TA, spA); fma2(QA, TB, spA);
            fma2(PB, TA, spB); fma2(QB, TB, spB);
        }
        float2 pA = unpack2(PA), qA = unpack2(QA);
        float2 pB = unpack2(PB), qB = unpack2(QB);
        epilogue(n,     lane, make_float2(pA.x + pA.y, qA.x + qA.y),
                 slot, npairs, wr_next, usrc, wdst, p);
        epilogue(n + 1, lane, make_float2(pB.x + pB.y, qB.x + qB.y),
                 slot, npairs, wr_next, usrc, wdst, p);
    }
    if (n < ne) {
        int r0 = g_rowptr[n], r1 = g_rowptr[n + 1];
        float2 acc, dummy;
        gather2(eg, wv, r0, r1, r1, r1, lane, acc, dummy);
        __syncwarp();
        su->mix.s[warp][0][lane] = pack2(acc);
        __syncwarp();
        ull PA = 0ull, QA = 0ull;
#pragma unroll
        for (int m = 0; m < 32; ++m) {
            ull spA = su->mix.s[warp][0][m];
            fma2(PA, su->mix.A[m][lane], spA);
            fma2(QA, su->mix.B[m][lane], spA);
        }
        float2 pA = unpack2(PA), qA = unpack2(QA);
        epilogue(n, lane, make_float2(pA.x + pA.y, qA.x + qA.y),
                 slot, npairs, wr_next, usrc, wdst, p);
    }

#pragma unroll
    for (int j = 0; j < 5; ++j)
        for (int off = 16; off > 0; off >>= 1)
            p[j] += __shfl_down_sync(0xffffffffu, p[j], off);
    __syncthreads();
    if (lane == 0)
        for (int j = 0; j < 5; ++j) red[warp][j] = (double)p[j];
    __syncthreads();
    if (threadIdx.x < npairs) {
        int j = threadIdx.x;
        double s = 0.0;
        for (int ww = 0; ww < WPB; ww++) s += red[ww][j];
        atomicAdd(&target[j], s);
    }
}

// ---------------- combine(k): Gram merge + 5x5 solve + u_new (+ fused decode at k=4) ----------------
__device__ void combine_phase(int k, float* sa, const float* __restrict__ decW,
                              float* __restrict__ out) {
    if (threadIdx.x == 0) {
        double M[5][5];
        const double* base = g_GGbuf[k & 1];
        int c = 0;
        for (int i = 0; i < 5; i++)
            for (int j = 0; j <= i; j++) { M[i][j] = base[c]; M[j][i] = base[c]; c++; }
        if (k > 0) {
            int idx = k - 1;
            const double* row = g_GGrow[(k - 1) & 1];
            for (int j = 0; j < 5; j++) { M[idx][j] = row[j]; M[j][idx] = row[j]; }
        }
        if (blockIdx.x == 0 && k < AAM - 1) {
            c = 0;
            for (int i = 0; i < 5; i++)
                for (int j = 0; j <= i; j++) g_GGbuf[(k + 1) & 1][c++] = M[i][j];
            for (int j = 0; j < 5; j++) g_GGrow[k & 1][j] = 0.0;
        }
        float A[5][6];
        for (int i = 0; i < 5; i++) {
            for (int j = 0; j < 5; j++) A[i][j] = (float)M[i][j];
            A[i][i] += 1e-4f;
            A[i][5] = 1.f;
        }
        for (int kk = 0; kk < 5; kk++) {
            int piv = kk; float mx = fabsf(A[kk][kk]);
            for (int r = kk + 1; r < 5; r++)
                if (fabsf(A[r][kk]) > mx) { mx = fabsf(A[r][kk]); piv = r; }
            if (piv != kk)
                for (int j = 0; j < 6; j++) { float t = A[kk][j]; A[kk][j] = A[piv][j]; A[piv][j] = t; }
            float inv = 1.f / A[kk][kk];
            for (int r = kk + 1; r < 5; r++) {
                float f = A[r][kk] * inv;
                for (int j = kk; j < 6; j++) A[r][j] -= f * A[kk][j];
            }
        }
        float a[5];
        for (int kk = 4; kk >= 0; kk--) {
            float s = A[kk][5];
            for (int j = kk + 1; j < 5; j++) s -= A[kk][j] * a[j];
            a[kk] = s / A[kk][kk];
        }
        float sum = a[0] + a[1] + a[2] + a[3] + a[4];
        for (int j = 0; j < 5; j++) sa[j] = a[j] / sum;
    }
    __syncthreads();
    float a0 = sa[0], a1 = sa[1], a2 = sa[2], a3 = sa[3], a4 = sa[4];

    int warp = threadIdx.x >> 5, lane = threadIdx.x & 31;
    int g = blockIdx.x * WPB + warp;
    const float2* F0 = (const float2*)g_F[0];
    const float2* F1 = (const float2*)g_F[1];
    const float2* F2 = (const float2*)g_F[2];
    const float2* F3 = (const float2*)g_F[3];
    const float2* F4 = (const float2*)g_F[4];
    for (int node = g; node < N_NODES; node += NWARPS) {
        int idx = node * 32 + lane;
        float2 f0 = F0[idx], f1 = F1[idx], f2 = F2[idx], f3 = F3[idx], f4 = F4[idx];
        float2 un;
        un.x = a0 * f0.x + a1 * f1.x + a2 * f2.x + a3 * f3.x + a4 * f4.x;
        un.y = a0 * f0.y + a1 * f1.y + a2 * f2.y + a3 * f3.y + a4 * f4.y;
        if (k < AAM - 1) {
            ((float2*)g_u)[idx] = un;
            float2 bb = ((const float2*)g_b)[idx];
            ((float2*)g_wbuf[0])[idx] =
                make_float2(2.f * fmaxf(un.x, 0.f) - un.x + bb.x,
                            2.f * fmaxf(un.y, 0.f) - un.y + bb.y);
        } else {
            float rx = fmaxf(un.x, 0.f), ry = fmaxf(un.y, 0.f);
            int o = lane & 15, half = lane >> 4;
            float acc = 0.f;
#pragma unroll
            for (int i = 0; i < 16; i++) {
                int m = half * 16 + i;
                float sx = __shfl_sync(0xffffffffu, rx, m);
                float sy = __shfl_sync(0xffffffffu, ry, m);
                acc = fmaf(sx, decW[(2 * m) * 16 + o], acc);
                acc = fmaf(sy, decW[(2 * m + 1) * 16 + o], acc);
            }
            acc += __shfl_down_sync(0xffffffffu, acc, 16);
            if (half == 0) out[node * 16 + o] = acc;
        }
    }
}

// ---------------- the single persistent kernel ----------------
__global__ void __launch_bounds__(TPB, BLK_PER_SM) k_mega(
    const float* __restrict__ x, const int* __restrict__ ei,
    const float* __restrict__ ew, const float* __restrict__ encW,
    const float* __restrict__ encb, const float* __restrict__ cayB,
    const float* __restrict__ decW, float* __restrict__ out)
{
    __shared__ SmemU su;
    __shared__ double red[WPB][5];
    __shared__ float sa[5];

    const int* src = ei;
    const int* dst = ei + N_EDGES;
    int gtid = blockIdx.x * TPB + threadIdx.x;

    // A: zero counters + Gram buf
    for (int i = gtid; i < N_NODES; i += NTHREADS) g_cur[i] = 0;
    if (gtid < 15) g_GGbuf[0][gtid] = 0.0;
    gbar();

    // B: degree histogram || encoder + b/w0
    for (int e = gtid; e < N_EDGES; e += NTHREADS) atomicAdd(&g_cur[dst[e]], 1);
    encode_phase(x, encW, encb);
    gbar();

    // C: prefix scan (block 0) || Cayley theta (block 1)
    if (blockIdx.x == 0) {
        int t = threadIdx.x;
        const int CH = (N_NODES + TPB - 1) / TPB;   // 10
        int beg = t * CH, end = beg + CH; if (end > N_NODES) end = N_NODES;
        if (beg > N_NODES) beg = N_NODES;
        int s = 0;
        for (int i = beg; i < end; i++) s += g_cur[i];
        su.part[t] = s;
        __syncthreads();
        for (int d = 1; d < TPB; d <<= 1) {
            int v = (t >= d) ? su.part[t - d] : 0;
            __syncthreads();
            su.part[t] += v;
            __syncthreads();
        }
        int off = (t > 0) ? su.part[t - 1] : 0;
        for (int i = beg; i < end; i++) {
            int c = g_cur[i];
            g_rowptr[i] = off;
            g_cur[i]    = off;
            off += c;
        }
        if (t == 0) g_rowptr[N_NODES] = N_EDGES;
    } else if (blockIdx.x == 1) {
        theta_phase(cayB, &su);
    }
    gbar();

    // D: CSR scatter || balanced warp partition || stage dual Theta layouts
    for (int e = gtid; e < N_EDGES; e += NTHREADS) {
        int d = dst[e];
        int p = atomicAdd(&g_cur[d], 1);
        g_edge[p] = make_int2(src[e], __float_as_int(ew[e]));
    }
    if (gtid <= NWARPS) {
        if (gtid == NWARPS) {
            g_wstart[NWARPS] = N_NODES;
        } else {
            long long target = (long long)gtid * COST_TOTAL / NWARPS;
            int lo = 0, hi = N_NODES;
            while (lo < hi) {
                int mid = (lo + hi) >> 1;
                long long c = (long long)g_rowptr[mid] + (long long)NODE_COST * mid;
                if (c < target) lo = mid + 1; else hi = mid;
            }
            g_wstart[gtid] = lo;
        }
    }
    for (int i = threadIdx.x; i < 1024; i += TPB) {
        int m = i >> 5, l = i & 31;
        float a0 = g_ThT[(2 * m) * 64 + 2 * l];
        float a1 = g_ThT[(2 * m + 1) * 64 + 2 * l];
        float b0 = g_ThT[(2 * m) * 64 + 2 * l + 1];
        float b1 = g_ThT[(2 * m + 1) * 64 + 2 * l + 1];
        su.mix.A[m][l] = pack2(make_float2(a0, a1));
        su.mix.B[m][l] = pack2(make_float2(b0, b1));
    }
    gbar();

    // history: 5 PR sweeps (w ping-pong); uu read from b / F[i-1] (no g_u traffic)
    for (int i = 0; i < AAM; i++) {
        spmm_phase(i, i + 1, &g_GGbuf[0][i * (i + 1) / 2], (i < AAM - 1) ? 1 : 0,
                   g_wbuf[i & 1], (i == 0) ? g_b : g_F[i - 1], g_wbuf[(i + 1) & 1],
                   &su, red);
        gbar();
    }

    // Anderson: combine -> spmm (last g() dead); final combine fuses decode
    for (int k = 0; k < AAM; k++) {
        combine_phase(k, sa, decW, out);
        if (k < AAM - 1) {
            gbar();
            spmm_phase(k, 5, g_GGrow[k & 1], 0, g_wbuf[0], g_u, 0, &su, red);
            gbar();
        }
    }
}

// ---------------- launch: ONE kernel ----------------
extern "C" void kernel_launch(void* const* d_in, const int* in_sizes, int n_in,
                              void* d_out, int out_size) {
    const float* x    = (const float*)d_in[0];
    const int*   ei   = (const int*)  d_in[1];
    const float* ew   = (const float*)d_in[2];
    const float* encW = (const float*)d_in[3];
    const float* encb = (const float*)d_in[4];
    const float* cayB = (const float*)d_in[5];
    const float* decW = (const float*)d_in[6];
    float* out = (float*)d_out;

    k_mega<<<GRID_BLOCKS, TPB>>>(x, ei, ew, encW, encb, cayB, decW, out);
}

// round 11
// speedup vs baseline: 1.0917x; 1.0215x over previous
#include <cuda_runtime.h>

#define N_NODES 10000
#define N_EDGES 320000
#define D_IN    128
#define D_HID   64
#define D_OUT   16
#define NH      (N_NODES * D_HID)
#define AAM     5
#define TPB         512
#define BLK_PER_SM  2
#define GRID_BLOCKS 296              // 148 SMs x 2 blocks guaranteed resident
#define WPB         (TPB / 32)       // 16
#define NWARPS      (GRID_BLOCKS * WPB)          // 4736
#define NTHREADS    (GRID_BLOCKS * TPB)
#define NODE_COST   48
#define COST_TOTAL  (N_EDGES + NODE_COST * N_NODES)

typedef unsigned long long ull;

// ---------------- device scratch ----------------
__device__ float  g_b[NH];
__device__ float  g_u[NH];                // written only by Anderson combines
__device__ float  g_wbuf[2][NH];          // ping-pong SPMM input
__device__ float  g_F[AAM][NH];
__device__ float  g_G[AAM][NH];
__device__ float  g_ThT[D_HID * D_HID];   // ThT[k*64+c] = Theta[c][k]
__device__ int    g_rowptr[N_NODES + 1];
__device__ int    g_cur[N_NODES];
__device__ __align__(16) int2 g_edge[N_EDGES];
__device__ int    g_wstart[NWARPS + 1];
__device__ double g_GGbuf[2][15];
__device__ double g_GGrow[2][5];
__device__ unsigned          g_bar_cnt;
__device__ volatile unsigned g_bar_gen;

union SmemU {
    struct { float M[64][128]; float fct[64]; } th;            // 33 KB (setup)
    struct {
        ulonglong2 T[32][32];     // 16KB: {A[m][l], B[m][l]} packed Theta
        ulonglong2 s[WPB][32];    // 8KB: per-warp staged (sA, sB)
    } mix;                        // 24 KB (spmm phases)
    int part[TPB];
};

// ---------------- f32x2 helpers ----------------
__device__ __forceinline__ void fma2(ull& d, ull a, ull b) {
    asm("fma.rn.f32x2 %0, %1, %2, %0;" : "+l"(d) : "l"(a), "l"(b));
}
__device__ __forceinline__ ull pack2(float2 v) {
    ull r; asm("mov.b64 %0, {%1, %2};" : "=l"(r) : "f"(v.x), "f"(v.y)); return r;
}
__device__ __forceinline__ float2 unpack2(ull v) {
    float2 r; asm("mov.b64 {%0, %1}, %2;" : "=f"(r.x), "=f"(r.y) : "l"(v)); return r;
}
__device__ __forceinline__ float2 gfma(float2 a, float w, float2 v) {
    a.x = fmaf(w, v.x, a.x); a.y = fmaf(w, v.y, a.y); return a;
}

// ---------------- software grid barrier ----------------
__device__ __forceinline__ void gbar() {
    __syncthreads();
    if (threadIdx.x == 0) {
        __threadfence();
        unsigned gen = g_bar_gen;
        if (atomicAdd(&g_bar_cnt, 1u) == GRID_BLOCKS - 1u) {
            g_bar_cnt = 0u;
            __threadfence();
            g_bar_gen = gen + 1u;
        } else {
            while (g_bar_gen == gen) { __nanosleep(32); }
        }
        __threadfence();
    }
    __syncthreads();
}

// ---------------- Cayley: Theta = (I+Om)^-1 (I-Om) ----------------
__device__ void theta_phase(const float* __restrict__ B, SmemU* su) {
    int tid = threadIdx.x;
    for (int idx = tid; idx < 64 * 64; idx += TPB) {
        int i = idx >> 6, j = idx & 63;
        float om = 0.5f * (B[i * 64 + j] - B[j * 64 + i]);
        float e  = (i == j) ? 1.f : 0.f;
        su->th.M[i][j]      = e + om;
        su->th.M[i][64 + j] = e - om;
    }
    __syncthreads();
    for (int k = 0; k < 64; k++) {
        float inv = 1.f / su->th.M[k][k];
        __syncthreads();
        for (int j = tid; j < 128; j += TPB) su->th.M[k][j] *= inv;
        __syncthreads();
        for (int r = tid; r < 64; r += TPB) su->th.fct[r] = su->th.M[r][k];
        __syncthreads();
        for (int idx = tid; idx < 64 * 128; idx += TPB) {
            int r = idx >> 7, j = idx & 127;
            if (r != k) su->th.M[r][j] -= su->th.fct[r] * su->th.M[k][j];
        }
        __syncthreads();
    }
    for (int idx = tid; idx < 64 * 64; idx += TPB) {
        int k = idx >> 6, c = idx & 63;
        g_ThT[idx] = su->th.M[c][64 + k];
    }
}

// ---------------- encoder + b/w0 ----------------
__device__ void encode_phase(const float* __restrict__ x, const float* __restrict__ W,
                             const float* __restrict__ bias) {
    int warp = threadIdx.x >> 5, cp = threadIdx.x & 31;
    int g = blockIdx.x * WPB + warp;
    const float2* __restrict__ W2 = (const float2*)W;
    float2 bsv = ((const float2*)bias)[cp];
    for (int node = g; node < N_NODES; node += NWARPS) {
        const float* __restrict__ xr = x + node * D_IN;
        float2 acc = bsv;
#pragma unroll 16
        for (int k = 0; k < D_IN; k++) {
            float  xk = xr[k];
            float2 w2 = W2[k * 32 + cp];
            acc.x = fmaf(xk, w2.x, acc.x);
            acc.y = fmaf(xk, w2.y, acc.y);
        }
        int row = node * 32 + cp;
        ((float2*)g_b)[row] = acc;
        ((float2*)g_wbuf[0])[row] = make_float2(2.f * fmaxf(acc.x, 0.f),
                                                2.f * fmaxf(acc.y, 0.f));
    }
}

// ---------------- interleaved dual-node gather, int4 descriptors ----------------
__device__ __forceinline__ void gather2(const int2* __restrict__ eg,
                                        const float2* __restrict__ wv,
                                        int eA, int endA, int eB, int endB,
                                        int lane, float2& outA, float2& outB) {
    const int4* __restrict__ eg4 = (const int4*)eg;
    float2 aA0 = {0.f, 0.f}, aA1 = {0.f, 0.f};
    float2 aB0 = {0.f, 0.f}, aB1 = {0.f, 0.f};
    // odd-head fixup (keeps int4 loads 16B-aligned)
    if ((eA & 1) && eA < endA) {
        int2 d = eg[eA];
        aA0 = gfma(aA0, __int_as_float(d.y), wv[d.x * 32 + lane]);
        eA++;
    }
    if ((eB & 1) && eB < endB) {
        int2 d = eg[eB];
        aB0 = gfma(aB0, __int_as_float(d.y), wv[d.x * 32 + lane]);
        eB++;
    }
    int hA = eA >> 1, heA = endA >> 1;
    int hB = eB >> 1, heB = endB >> 1;
    // interleaved main loop: 8 edges (4 per node) in flight per iteration
    while (hA + 2 <= heA && hB + 2 <= heB) {
        int4 dA0 = eg4[hA], dA1 = eg4[hA + 1];
        int4 dB0 = eg4[hB], dB1 = eg4[hB + 1];
        float2 vA0 = wv[dA0.x * 32 + lane], vA1 = wv[dA0.z * 32 + lane];
        float2 vA2 = wv[dA1.x * 32 + lane], vA3 = wv[dA1.z * 32 + lane];
        float2 vB0 = wv[dB0.x * 32 + lane], vB1 = wv[dB0.z * 32 + lane];
        float2 vB2 = wv[dB1.x * 32 + lane], vB3 = wv[dB1.z * 32 + lane];
        aA0 = gfma(aA0, __int_as_float(dA0.y), vA0);
        aA1 = gfma(aA1, __int_as_float(dA0.w), vA1);
        aA0 = gfma(aA0, __int_as_float(dA1.y), vA2);
        aA1 = gfma(aA1, __int_as_float(dA1.w), vA3);
        aB0 = gfma(aB0, __int_as_float(dB0.y), vB0);
        aB1 = gfma(aB1, __int_as_float(dB0.w), vB1);
        aB0 = gfma(aB0, __int_as_float(dB1.y), vB2);
        aB1 = gfma(aB1, __int_as_float(dB1.w), vB3);
        hA += 2; hB += 2;
    }
    for (; hA < heA; ++hA) {
        int4 d = eg4[hA];
        aA0 = gfma(aA0, __int_as_float(d.y), wv[d.x * 32 + lane]);
        aA1 = gfma(aA1, __int_as_float(d.w), wv[d.z * 32 + lane]);
    }
    if ((endA & 1) && endA > eA) {
        int2 d = eg[endA - 1];
        aA0 = gfma(aA0, __int_as_float(d.y), wv[d.x * 32 + lane]);
    }
    for (; hB < heB; ++hB) {
        int4 d = eg4[hB];
        aB0 = gfma(aB0, __int_as_float(d.y), wv[d.x * 32 + lane]);
        aB1 = gfma(aB1, __int_as_float(d.w), wv[d.z * 32 + lane]);
    }
    if ((endB & 1) && endB > eB) {
        int2 d = eg[endB - 1];
        aB0 = gfma(aB0, __int_as_float(d.y), wv[d.x * 32 + lane]);
    }
    outA = make_float2(aA0.x + aA1.x, aA0.y + aA1.y);
    outB = make_float2(aB0.x + aB1.x, aB0.y + aB1.y);
}

// ---------------- per-node epilogue ----------------
__device__ __forceinline__ void epilogue(int node, int lane, float2 mix, int slot,
                                         int npairs, int wr_next, int wr_g,
                                         const float* __restrict__ usrc,
                                         float* __restrict__ wdst, float* p) {
    int row = node * 32 + lane;
    float2 bb = ((const float2*)g_b)[row];
    float2 uu = ((const float2*)usrc)[row];
    float2 val = make_float2(bb.x + 0.5f * mix.x, bb.y + 0.5f * mix.y);
    ((float2*)g_F[slot])[row] = val;
    float2 gn = make_float2(val.x - uu.x, val.y - uu.y);
    if (wr_g) ((float2*)g_G[slot])[row] = gn;
    if (wr_next) {
        ((float2*)wdst)[row] = make_float2(2.f * fmaxf(val.x, 0.f) - val.x + bb.x,
                                           2.f * fmaxf(val.y, 0.f) - val.y + bb.y);
    }
    for (int j = 0; j < npairs; ++j) {
        float2 gj = (j == slot) ? gn : ((const float2*)g_G[j])[row];
        p[j] = fmaf(gn.x, gj.x, fmaf(gn.y, gj.y, p[j]));
    }
}

// ---------------- fused SPMM + LDS.128 mix + G + Gram partials ----------------
__device__ void spmm_phase(int slot, int npairs, double* target, int wr_next, int wr_g,
                           const float* __restrict__ wsrc,
                           const float* __restrict__ usrc,
                           float* __restrict__ wdst,
                           SmemU* su, double (*red)[5]) {
    int warp = threadIdx.x >> 5, lane = threadIdx.x & 31;
    int w = blockIdx.x * WPB + warp;
    const int2*   __restrict__ eg = g_edge;
    const float2* __restrict__ wv = (const float2*)wsrc;
    float p[5];
#pragma unroll
    for (int j = 0; j < 5; j++) p[j] = 0.f;

    int n = g_wstart[w], ne = g_wstart[w + 1];

    for (; n + 1 < ne; n += 2) {
        int r0 = g_rowptr[n], r1 = g_rowptr[n + 1], r2 = g_rowptr[n + 2];
        float2 accA, accB;
        gather2(eg, wv, r0, r1, r1, r2, lane, accA, accB);

        __syncwarp();
        su->mix.s[warp][lane] = make_ulonglong2(pack2(accA), pack2(accB));
        __syncwarp();

        ull PA = 0ull, QA = 0ull, PB = 0ull, QB = 0ull;
#pragma unroll
        for (int m = 0; m < 32; ++m) {
            ulonglong2 sp = su->mix.s[warp][m];   // broadcast LDS.128
            ulonglong2 T  = su->mix.T[m][lane];   // conflict-free LDS.128
            fma2(PA, T.x, sp.x); fma2(QA, T.y, sp.x);
            fma2(PB, T.x, sp.y); fma2(QB, T.y, sp.y);
        }
        float2 pA = unpack2(PA), qA = unpack2(QA);
        float2 pB = unpack2(PB), qB = unpack2(QB);
        epilogue(n,     lane, make_float2(pA.x + pA.y, qA.x + qA.y),
                 slot, npairs, wr_next, wr_g, usrc, wdst, p);
        epilogue(n + 1, lane, make_float2(pB.x + pB.y, qB.x + qB.y),
                 slot, npairs, wr_next, wr_g, usrc, wdst, p);
    }
    if (n < ne) {
        int r0 = g_rowptr[n], r1 = g_rowptr[n + 1];
        float2 acc, dummy;
        gather2(eg, wv, r0, r1, r1, r1, lane, acc, dummy);
        __syncwarp();
        su->mix.s[warp][lane] = make_ulonglong2(pack2(acc), 0ull);
        __syncwarp();
        ull PA = 0ull, QA = 0ull;
#pragma unroll
        for (int m = 0; m < 32; ++m) {
            ulonglong2 sp = su->mix.s[warp][m];
            ulonglong2 T  = su->mix.T[m][lane];
            fma2(PA, T.x, sp.x);
            fma2(QA, T.y, sp.x);
        }
        float2 pA = unpack2(PA), qA = unpack2(QA);
        epilogue(n, lane, make_float2(pA.x + pA.y, qA.x + qA.y),
                 slot, npairs, wr_next, wr_g, usrc, wdst, p);
    }

#pragma unroll
    for (int j = 0; j < 5; ++j)
        for (int off = 16; off > 0; off >>= 1)
            p[j] += __shfl_down_sync(0xffffffffu, p[j], off);
    __syncthreads();
    if (lane == 0)
        for (int j = 0; j < 5; ++j) red[warp][j] = (double)p[j];
    __syncthreads();
    if (threadIdx.x < npairs) {
        int j = threadIdx.x;
        double s = 0.0;
        for (int ww = 0; ww < WPB; ww++) s += red[ww][j];
        atomicAdd(&target[j], s);
    }
}

// ---------------- combine(k): Gram merge + 5x5 solve + u_new (+ fused decode at k=4) ----------------
__device__ void combine_phase(int k, float* sa, const float* __restrict__ decW,
                              float* __restrict__ out) {
    if (threadIdx.x == 0) {
        double M[5][5];
        const double* base = g_GGbuf[k & 1];
        int c = 0;
        for (int i = 0; i < 5; i++)
            for (int j = 0; j <= i; j++) { M[i][j] = base[c]; M[j][i] = base[c]; c++; }
        if (k > 0) {
            int idx = k - 1;
            const double* row = g_GGrow[(k - 1) & 1];
            for (int j = 0; j < 5; j++) { M[idx][j] = row[j]; M[j][idx] = row[j]; }
        }
        if (blockIdx.x == 0 && k < AAM - 1) {
            c = 0;
            for (int i = 0; i < 5; i++)
                for (int j = 0; j <= i; j++) g_GGbuf[(k + 1) & 1][c++] = M[i][j];
            for (int j = 0; j < 5; j++) g_GGrow[k & 1][j] = 0.0;
        }
        float A[5][6];
        for (int i = 0; i < 5; i++) {
            for (int j = 0; j < 5; j++) A[i][j] = (float)M[i][j];
            A[i][i] += 1e-4f;
            A[i][5] = 1.f;
        }
        for (int kk = 0; kk < 5; kk++) {
            int piv = kk; float mx = fabsf(A[kk][kk]);
            for (int r = kk + 1; r < 5; r++)
                if (fabsf(A[r][kk]) > mx) { mx = fabsf(A[r][kk]); piv = r; }
            if (piv != kk)
                for (int j = 0; j < 6; j++) { float t = A[kk][j]; A[kk][j] = A[piv][j]; A[piv][j] = t; }
            float inv = 1.f / A[kk][kk];
            for (int r = kk + 1; r < 5; r++) {
                float f = A[r][kk] * inv;
                for (int j = kk; j < 6; j++) A[r][j] -= f * A[kk][j];
            }
        }
        float a[5];
        for (int kk = 4; kk >= 0; kk--) {
            float s = A[kk][5];
            for (int j = kk + 1; j < 5; j++) s -= A[kk][j] * a[j];
            a[kk] = s / A[kk][kk];
        }
        float sum = a[0] + a[1] + a[2] + a[3] + a[4];
        for (int j = 0; j < 5; j++) sa[j] = a[j] / sum;
    }
    __syncthreads();
    float a0 = sa[0], a1 = sa[1], a2 = sa[2], a3 = sa[3], a4 = sa[4];

    int warp = threadIdx.x >> 5, lane = threadIdx.x & 31;
    int g = blockIdx.x * WPB + warp;
    const float2* F0 = (const float2*)g_F[0];
    const float2* F1 = (const float2*)g_F[1];
    const float2* F2 = (const float2*)g_F[2];
    const float2* F3 = (const float2*)g_F[3];
    const float2* F4 = (const float2*)g_F[4];
    for (int node = g; node < N_NODES; node += NWARPS) {
        int idx = node * 32 + lane;
        float2 f0 = F0[idx], f1 = F1[idx], f2 = F2[idx], f3 = F3[idx], f4 = F4[idx];
        float2 un;
        un.x = a0 * f0.x + a1 * f1.x + a2 * f2.x + a3 * f3.x + a4 * f4.x;
        un.y = a0 * f0.y + a1 * f1.y + a2 * f2.y + a3 * f3.y + a4 * f4.y;
        if (k < AAM - 1) {
            ((float2*)g_u)[idx] = un;
            float2 bb = ((const float2*)g_b)[idx];
            ((float2*)g_wbuf[0])[idx] =
                make_float2(2.f * fmaxf(un.x, 0.f) - un.x + bb.x,
                            2.f * fmaxf(un.y, 0.f) - un.y + bb.y);
        } else {
            float rx = fmaxf(un.x, 0.f), ry = fmaxf(un.y, 0.f);
            int o = lane & 15, half = lane >> 4;
            float acc = 0.f;
#pragma unroll
            for (int i = 0; i < 16; i++) {
                int m = half * 16 + i;
                float sx = __shfl_sync(0xffffffffu, rx, m);
                float sy = __shfl_sync(0xffffffffu, ry, m);
                acc = fmaf(sx, decW[(2 * m) * 16 + o], acc);
                acc = fmaf(sy, decW[(2 * m + 1) * 16 + o], acc);
            }
            acc += __shfl_down_sync(0xffffffffu, acc, 16);
            if (half == 0) out[node * 16 + o] = acc;
        }
    }
}

// ---------------- the single persistent kernel ----------------
__global__ void __launch_bounds__(TPB, BLK_PER_SM) k_mega(
    const float* __restrict__ x, const int* __restrict__ ei,
    const float* __restrict__ ew, const float* __restrict__ encW,
    const float* __restrict__ encb, const float* __restrict__ cayB,
    const float* __restrict__ decW, float* __restrict__ out)
{
    __shared__ SmemU su;
    __shared__ double red[WPB][5];
    __shared__ float sa[5];

    const int* src = ei;
    const int* dst = ei + N_EDGES;
    int gtid = blockIdx.x * TPB + threadIdx.x;

    // A: zero counters + Gram buf
    for (int i = gtid; i < N_NODES; i += NTHREADS) g_cur[i] = 0;
    if (gtid < 15) g_GGbuf[0][gtid] = 0.0;
    gbar();

    // B: degree histogram || encoder + b/w0
    for (int e = gtid; e < N_EDGES; e += NTHREADS) atomicAdd(&g_cur[dst[e]], 1);
    encode_phase(x, encW, encb);
    gbar();

    // C: prefix scan (block 0) || Cayley theta (block 1)
    if (blockIdx.x == 0) {
        int t = threadIdx.x;
        const int CH = (N_NODES + TPB - 1) / TPB;   // 20
        int beg = t * CH, end = beg + CH; if (end > N_NODES) end = N_NODES;
        int s = 0;
        for (int i = beg; i < end; i++) s += g_cur[i];
        su.part[t] = s;
        __syncthreads();
        for (int d = 1; d < TPB; d <<= 1) {
            int v = (t >= d) ? su.part[t - d] : 0;
            __syncthreads();
            su.part[t] += v;
            __syncthreads();
        }
        int off = (t > 0) ? su.part[t - 1] : 0;
        for (int i = beg; i < end; i++) {
            int c = g_cur[i];
            g_rowptr[i] = off;
            g_cur[i]    = off;
            off += c;
        }
        if (t == 0) g_rowptr[N_NODES] = N_EDGES;
    } else if (blockIdx.x == 1) {
        theta_phase(cayB, &su);
    }
    gbar();

    // D: CSR scatter || balanced warp partition || stage packed Theta (ull2)
    for (int e = gtid; e < N_EDGES; e += NTHREADS) {
        int d = dst[e];
        int p = atomicAdd(&g_cur[d], 1);
        g_edge[p] = make_int2(src[e], __float_as_int(ew[e]));
    }
    if (gtid <= NWARPS) {
        if (gtid == NWARPS) {
            g_wstart[NWARPS] = N_NODES;
        } else {
            long long target = (long long)gtid * COST_TOTAL / NWARPS;
            int lo = 0, hi = N_NODES;
            while (lo < hi) {
                int mid = (lo + hi) >> 1;
                long long c = (long long)g_rowptr[mid] + (long long)NODE_COST * mid;
                if (c < target) lo = mid + 1; else hi = mid;
            }
            g_wstart[gtid] = lo;
        }
    }
    for (int i = threadIdx.x; i < 1024; i += TPB) {
        int m = i >> 5, l = i & 31;
        float a0 = g_ThT[(2 * m) * 64 + 2 * l];
        float a1 = g_ThT[(2 * m + 1) * 64 + 2 * l];
        float b0 = g_ThT[(2 * m) * 64 + 2 * l + 1];
        float b1 = g_ThT[(2 * m + 1) * 64 + 2 * l + 1];
        su.mix.T[m][l] = make_ulonglong2(pack2(make_float2(a0, a1)),
                                         pack2(make_float2(b0, b1)));
    }
    gbar();

    // history: 5 PR sweeps (w ping-pong); uu read from b / F[i-1]
    for (int i = 0; i < AAM; i++) {
        spmm_phase(i, i + 1, &g_GGbuf[0][i * (i + 1) / 2], (i < AAM - 1) ? 1 : 0, 1,
                   g_wbuf[i & 1], (i == 0) ? g_b : g_F[i - 1], g_wbuf[(i + 1) & 1],
                   &su, red);
        gbar();
    }

    // Anderson: combine -> spmm (last g() dead); final combine fuses decode.
    // G store is dead in the last executed Anderson spmm (k == AAM-2).
    for (int k = 0; k < AAM; k++) {
        combine_phase(k, sa, decW, out);
        if (k < AAM - 1) {
            gbar();
            spmm_phase(k, 5, g_GGrow[k & 1], 0, (k < AAM - 2) ? 1 : 0,
                       g_wbuf[0], g_u, 0, &su, red);
            gbar();
        }
    }
}

// ---------------- launch: ONE kernel ----------------
extern "C" void kernel_launch(void* const* d_in, const int* in_sizes, int n_in,
                              void* d_out, int out_size) {
    const float* x    = (const float*)d_in[0];
    const int*   ei   = (const int*)  d_in[1];
    const float* ew   = (const float*)d_in[2];
    const float* encW = (const float*)d_in[3];
    const float* encb = (const float*)d_in[4];
    const float* cayB = (const float*)d_in[5];
    const float* decW = (const float*)d_in[6];
    float* out = (float*)d_out;

    k_mega<<<GRID_BLOCKS, TPB>>>(x, ei, ew, encW, encb, cayB, decW, out);
}

// round 12
// speedup vs baseline: 1.1314x; 1.0364x over previous
#include <cuda_runtime.h>

#define N_NODES 10000
#define N_EDGES 320000
#define D_IN    128
#define D_HID   64
#define D_OUT   16
#define NH      (N_NODES * D_HID)
#define AAM     5
#define PAD     128                  // padded edge-row length (max degree ~ 32 + 11 sigma << 128)
#define TPB         512
#define BLK_PER_SM  2
#define GRID_BLOCKS 296              // 148 SMs x 2 blocks guaranteed resident
#define WPB         (TPB / 32)       // 16
#define NWARPS      (GRID_BLOCKS * WPB)          // 4736
#define NTHREADS    (GRID_BLOCKS * TPB)
#define NODE_COST   48
#define COST_TOTAL  (N_EDGES + NODE_COST * N_NODES)

typedef unsigned long long ull;

// ---------------- device scratch ----------------
__device__ float  g_b[NH];
__device__ float  g_u[NH];                // written only by Anderson combines
__device__ float  g_wbuf[2][NH];          // ping-pong SPMM input
__device__ float  g_F[AAM][NH];
__device__ float  g_G[AAM][NH];
__device__ float  g_ThT[D_HID * D_HID];   // ThT[k*64+c] = Theta[c][k]
__device__ int    g_rowptr[N_NODES + 1];  // prefix of counts (partition only)
__device__ int    g_cur[N_NODES];         // zero at launch entry (zeroed at prior kernel end / static init)
__device__ __align__(16) int2 g_edge[N_NODES * PAD];   // padded edge rows
__device__ int    g_wstart[NWARPS + 1];
__device__ double g_GGbuf[2][15];
__device__ double g_GGrow[2][5];
__device__ unsigned          g_bar_cnt;
__device__ volatile unsigned g_bar_gen;

union SmemU {
    struct { float M[64][128]; float fct[64]; } th;            // 33 KB (setup)
    struct {
        ulonglong2 T[32][32];     // 16KB: {A[m][l], B[m][l]} packed Theta
        ulonglong2 s[WPB][32];    // 8KB: per-warp staged (sA, sB) / encoder x rows
    } mix;                        // 24 KB
    int part[TPB];
};

// ---------------- f32x2 helpers ----------------
__device__ __forceinline__ void fma2(ull& d, ull a, ull b) {
    asm("fma.rn.f32x2 %0, %1, %2, %0;" : "+l"(d) : "l"(a), "l"(b));
}
__device__ __forceinline__ ull pack2(float2 v) {
    ull r; asm("mov.b64 %0, {%1, %2};" : "=l"(r) : "f"(v.x), "f"(v.y)); return r;
}
__device__ __forceinline__ float2 unpack2(ull v) {
    float2 r; asm("mov.b64 {%0, %1}, %2;" : "=f"(r.x), "=f"(r.y) : "l"(v)); return r;
}
__device__ __forceinline__ float2 gfma(float2 a, float w, float2 v) {
    a.x = fmaf(w, v.x, a.x); a.y = fmaf(w, v.y, a.y); return a;
}

// ---------------- software grid barrier ----------------
__device__ __forceinline__ void gbar() {
    __syncthreads();
    if (threadIdx.x == 0) {
        __threadfence();
        unsigned gen = g_bar_gen;
        if (atomicAdd(&g_bar_cnt, 1u) == GRID_BLOCKS - 1u) {
            g_bar_cnt = 0u;
            __threadfence();
            g_bar_gen = gen + 1u;
        } else {
            while (g_bar_gen == gen) { __nanosleep(32); }
        }
        __threadfence();
    }
    __syncthreads();
}

// ---------------- Cayley: Theta = (I+Om)^-1 (I-Om) ----------------
__device__ void theta_phase(const float* __restrict__ B, SmemU* su) {
    int tid = threadIdx.x;
    for (int idx = tid; idx < 64 * 64; idx += TPB) {
        int i = idx >> 6, j = idx & 63;
        float om = 0.5f * (B[i * 64 + j] - B[j * 64 + i]);
        float e  = (i == j) ? 1.f : 0.f;
        su->th.M[i][j]      = e + om;
        su->th.M[i][64 + j] = e - om;
    }
    __syncthreads();
    for (int k = 0; k < 64; k++) {
        float inv = 1.f / su->th.M[k][k];
        __syncthreads();
        for (int j = tid; j < 128; j += TPB) su->th.M[k][j] *= inv;
        __syncthreads();
        for (int r = tid; r < 64; r += TPB) su->th.fct[r] = su->th.M[r][k];
        __syncthreads();
        for (int idx = tid; idx < 64 * 128; idx += TPB) {
            int r = idx >> 7, j = idx & 127;
            if (r != k) su->th.M[r][j] -= su->th.fct[r] * su->th.M[k][j];
        }
        __syncthreads();
    }
    for (int idx = tid; idx < 64 * 64; idx += TPB) {
        int k = idx >> 6, c = idx & 63;
        g_ThT[idx] = su->th.M[c][64 + k];
    }
}

// ---------------- encoder + b/w0 (x staged through smem, coalesced) ----------------
__device__ void encode_phase(const float* __restrict__ x, const float* __restrict__ W,
                             const float* __restrict__ bias, SmemU* su) {
    int warp = threadIdx.x >> 5, cp = threadIdx.x & 31;
    int g = blockIdx.x * WPB + warp;
    const float2* __restrict__ W2 = (const float2*)W;
    float4* sx = (float4*)&su->mix.s[warp][0];   // 512B = one x row
    float2 bsv = ((const float2*)bias)[cp];
    for (int node = g; node < N_NODES; node += NWARPS) {
        sx[cp] = ((const float4*)(x + node * D_IN))[cp];   // 4 LDG.128 worth, coalesced
        __syncwarp();
        const float* xs = (const float*)sx;
        float2 acc = bsv;
#pragma unroll 16
        for (int k = 0; k < D_IN; k++) {
            float  xk = xs[k];                              // broadcast LDS
            float2 w2 = W2[k * 32 + cp];
            acc.x = fmaf(xk, w2.x, acc.x);
            acc.y = fmaf(xk, w2.y, acc.y);
        }
        __syncwarp();
        int row = node * 32 + cp;
        ((float2*)g_b)[row] = acc;
        ((float2*)g_wbuf[0])[row] = make_float2(2.f * fmaxf(acc.x, 0.f),
                                                2.f * fmaxf(acc.y, 0.f));
    }
}

// ---------------- interleaved dual-node gather (padded rows, int4 descriptors) ----------------
__device__ __forceinline__ void gather2(const int2* __restrict__ eg,
                                        const float2* __restrict__ wv,
                                        int bA, int cA, int bB, int cB,
                                        int lane, float2& outA, float2& outB) {
    const int4* __restrict__ e4A = (const int4*)(eg + bA);   // rows are 16B-aligned
    const int4* __restrict__ e4B = (const int4*)(eg + bB);
    float2 aA0 = {0.f, 0.f}, aA1 = {0.f, 0.f};
    float2 aB0 = {0.f, 0.f}, aB1 = {0.f, 0.f};
    int hA = 0, heA = cA >> 1;
    int hB = 0, heB = cB >> 1;
    while (hA + 2 <= heA && hB + 2 <= heB) {
        int4 dA0 = e4A[hA], dA1 = e4A[hA + 1];
        int4 dB0 = e4B[hB], dB1 = e4B[hB + 1];
        float2 vA0 = wv[dA0.x * 32 + lane], vA1 = wv[dA0.z * 32 + lane];
        float2 vA2 = wv[dA1.x * 32 + lane], vA3 = wv[dA1.z * 32 + lane];
        float2 vB0 = wv[dB0.x * 32 + lane], vB1 = wv[dB0.z * 32 + lane];
        float2 vB2 = wv[dB1.x * 32 + lane], vB3 = wv[dB1.z * 32 + lane];
        aA0 = gfma(aA0, __int_as_float(dA0.y), vA0);
        aA1 = gfma(aA1, __int_as_float(dA0.w), vA1);
        aA0 = gfma(aA0, __int_as_float(dA1.y), vA2);
        aA1 = gfma(aA1, __int_as_float(dA1.w), vA3);
        aB0 = gfma(aB0, __int_as_float(dB0.y), vB0);
        aB1 = gfma(aB1, __int_as_float(dB0.w), vB1);
        aB0 = gfma(aB0, __int_as_float(dB1.y), vB2);
        aB1 = gfma(aB1, __int_as_float(dB1.w), vB3);
        hA += 2; hB += 2;
    }
    for (; hA < heA; ++hA) {
        int4 d = e4A[hA];
        aA0 = gfma(aA0, __int_as_float(d.y), wv[d.x * 32 + lane]);
        aA1 = gfma(aA1, __int_as_float(d.w), wv[d.z * 32 + lane]);
    }
    if (cA & 1) {
        int2 d = eg[bA + cA - 1];
        aA0 = gfma(aA0, __int_as_float(d.y), wv[d.x * 32 + lane]);
    }
    for (; hB < heB; ++hB) {
        int4 d = e4B[hB];
        aB0 = gfma(aB0, __int_as_float(d.y), wv[d.x * 32 + lane]);
        aB1 = gfma(aB1, __int_as_float(d.w), wv[d.z * 32 + lane]);
    }
    if (cB & 1) {
        int2 d = eg[bB + cB - 1];
        aB0 = gfma(aB0, __int_as_float(d.y), wv[d.x * 32 + lane]);
    }
    outA = make_float2(aA0.x + aA1.x, aA0.y + aA1.y);
    outB = make_float2(aB0.x + aB1.x, aB0.y + aB1.y);
}

// ---------------- per-node epilogue ----------------
__device__ __forceinline__ void epilogue(int node, int lane, float2 mix, int slot,
                                         int npairs, int wr_next, int wr_g,
                                         const float* __restrict__ usrc,
                                         float* __restrict__ wdst, float* p) {
    int row = node * 32 + lane;
    float2 bb = ((const float2*)g_b)[row];
    float2 uu = ((const float2*)usrc)[row];
    float2 val = make_float2(bb.x + 0.5f * mix.x, bb.y + 0.5f * mix.y);
    ((float2*)g_F[slot])[row] = val;
    float2 gn = make_float2(val.x - uu.x, val.y - uu.y);
    if (wr_g) ((float2*)g_G[slot])[row] = gn;
    if (wr_next) {
        ((float2*)wdst)[row] = make_float2(2.f * fmaxf(val.x, 0.f) - val.x + bb.x,
                                           2.f * fmaxf(val.y, 0.f) - val.y + bb.y);
    }
    for (int j = 0; j < npairs; ++j) {
        float2 gj = (j == slot) ? gn : ((const float2*)g_G[j])[row];
        p[j] = fmaf(gn.x, gj.x, fmaf(gn.y, gj.y, p[j]));
    }
}

// ---------------- fused SPMM + LDS.128 mix + G + Gram partials ----------------
__device__ void spmm_phase(int slot, int npairs, double* target, int wr_next, int wr_g,
                           const float* __restrict__ wsrc,
                           const float* __restrict__ usrc,
                           float* __restrict__ wdst,
                           SmemU* su, double (*red)[5]) {
    int warp = threadIdx.x >> 5, lane = threadIdx.x & 31;
    int w = blockIdx.x * WPB + warp;
    const int2*   __restrict__ eg = g_edge;
    const float2* __restrict__ wv = (const float2*)wsrc;
    float p[5];
#pragma unroll
    for (int j = 0; j < 5; j++) p[j] = 0.f;

    int n = g_wstart[w], ne = g_wstart[w + 1];

    for (; n + 1 < ne; n += 2) {
        int cA = g_cur[n], cB = g_cur[n + 1];
        float2 accA, accB;
        gather2(eg, wv, n * PAD, cA, (n + 1) * PAD, cB, lane, accA, accB);

        __syncwarp();
        su->mix.s[warp][lane] = make_ulonglong2(pack2(accA), pack2(accB));
        __syncwarp();

        ull PA = 0ull, QA = 0ull, PB = 0ull, QB = 0ull;
#pragma unroll
        for (int m = 0; m < 32; ++m) {
            ulonglong2 sp = su->mix.s[warp][m];   // broadcast LDS.128
            ulonglong2 T  = su->mix.T[m][lane];   // conflict-free LDS.128
            fma2(PA, T.x, sp.x); fma2(QA, T.y, sp.x);
            fma2(PB, T.x, sp.y); fma2(QB, T.y, sp.y);
        }
        float2 pA = unpack2(PA), qA = unpack2(QA);
        float2 pB = unpack2(PB), qB = unpack2(QB);
        epilogue(n,     lane, make_float2(pA.x + pA.y, qA.x + qA.y),
                 slot, npairs, wr_next, wr_g, usrc, wdst, p);
        epilogue(n + 1, lane, make_float2(pB.x + pB.y, qB.x + qB.y),
                 slot, npairs, wr_next, wr_g, usrc, wdst, p);
    }
    if (n < ne) {
        int cA = g_cur[n];
        float2 acc, dummy;
        gather2(eg, wv, n * PAD, cA, n * PAD, 0, lane, acc, dummy);
        __syncwarp();
        su->mix.s[warp][lane] = make_ulonglong2(pack2(acc), 0ull);
        __syncwarp();
        ull PA = 0ull, QA = 0ull;
#pragma unroll
        for (int m = 0; m < 32; ++m) {
            ulonglong2 sp = su->mix.s[warp][m];
            ulonglong2 T  = su->mix.T[m][lane];
            fma2(PA, T.x, sp.x);
            fma2(QA, T.y, sp.x);
        }
        float2 pA = unpack2(PA), qA = unpack2(QA);
        epilogue(n, lane, make_float2(pA.x + pA.y, qA.x + qA.y),
                 slot, npairs, wr_next, wr_g, usrc, wdst, p);
    }

#pragma unroll
    for (int j = 0; j < 5; ++j)
        for (int off = 16; off > 0; off >>= 1)
            p[j] += __shfl_down_sync(0xffffffffu, p[j], off);
    __syncthreads();
    if (lane == 0)
        for (int j = 0; j < 5; ++j) red[warp][j] = (double)p[j];
    __syncthreads();
    if (threadIdx.x < npairs) {
        int j = threadIdx.x;
        double s = 0.0;
        for (int ww = 0; ww < WPB; ww++) s += red[ww][j];
        atomicAdd(&target[j], s);
    }
}

// ---------------- combine(k): Gram merge + 5x5 solve + u_new (+ fused decode at k=4) ----------------
__device__ void combine_phase(int k, float* sa, const float* __restrict__ decW,
                              float* __restrict__ out) {
    if (threadIdx.x == 0) {
        double M[5][5];
        const double* base = g_GGbuf[k & 1];
        int c = 0;
        for (int i = 0; i < 5; i++)
            for (int j = 0; j <= i; j++) { M[i][j] = base[c]; M[j][i] = base[c]; c++; }
        if (k > 0) {
            int idx = k - 1;
            const double* row = g_GGrow[(k - 1) & 1];
            for (int j = 0; j < 5; j++) { M[idx][j] = row[j]; M[j][idx] = row[j]; }
        }
        if (blockIdx.x == 0 && k < AAM - 1) {
            c = 0;
            for (int i = 0; i < 5; i++)
                for (int j = 0; j <= i; j++) g_GGbuf[(k + 1) & 1][c++] = M[i][j];
            for (int j = 0; j < 5; j++) g_GGrow[k & 1][j] = 0.0;
        }
        float A[5][6];
        for (int i = 0; i < 5; i++) {
            for (int j = 0; j < 5; j++) A[i][j] = (float)M[i][j];
            A[i][i] += 1e-4f;
            A[i][5] = 1.f;
        }
        for (int kk = 0; kk < 5; kk++) {
            int piv = kk; float mx = fabsf(A[kk][kk]);
            for (int r = kk + 1; r < 5; r++)
                if (fabsf(A[r][kk]) > mx) { mx = fabsf(A[r][kk]); piv = r; }
            if (piv != kk)
                for (int j = 0; j < 6; j++) { float t = A[kk][j]; A[kk][j] = A[piv][j]; A[piv][j] = t; }
            float inv = 1.f / A[kk][kk];
            for (int r = kk + 1; r < 5; r++) {
                float f = A[r][kk] * inv;
                for (int j = kk; j < 6; j++) A[r][j] -= f * A[kk][j];
            }
        }
        float a[5];
        for (int kk = 4; kk >= 0; kk--) {
            float s = A[kk][5];
            for (int j = kk + 1; j < 5; j++) s -= A[kk][j] * a[j];
            a[kk] = s / A[kk][kk];
        }
        float sum = a[0] + a[1] + a[2] + a[3] + a[4];
        for (int j = 0; j < 5; j++) sa[j] = a[j] / sum;
    }
    __syncthreads();
    float a0 = sa[0], a1 = sa[1], a2 = sa[2], a3 = sa[3], a4 = sa[4];

    int warp = threadIdx.x >> 5, lane = threadIdx.x & 31;
    int g = blockIdx.x * WPB + warp;
    const float2* F0 = (const float2*)g_F[0];
    const float2* F1 = (const float2*)g_F[1];
    const float2* F2 = (const float2*)g_F[2];
    const float2* F3 = (const float2*)g_F[3];
    const float2* F4 = (const float2*)g_F[4];
    for (int node = g; node < N_NODES; node += NWARPS) {
        int idx = node * 32 + lane;
        float2 f0 = F0[idx], f1 = F1[idx], f2 = F2[idx], f3 = F3[idx], f4 = F4[idx];
        float2 un;
        un.x = a0 * f0.x + a1 * f1.x + a2 * f2.x + a3 * f3.x + a4 * f4.x;
        un.y = a0 * f0.y + a1 * f1.y + a2 * f2.y + a3 * f3.y + a4 * f4.y;
        if (k < AAM - 1) {
            ((float2*)g_u)[idx] = un;
            float2 bb = ((const float2*)g_b)[idx];
            ((float2*)g_wbuf[0])[idx] =
                make_float2(2.f * fmaxf(un.x, 0.f) - un.x + bb.x,
                            2.f * fmaxf(un.y, 0.f) - un.y + bb.y);
        } else {
            float rx = fmaxf(un.x, 0.f), ry = fmaxf(un.y, 0.f);
            int o = lane & 15, half = lane >> 4;
            float acc = 0.f;
#pragma unroll
            for (int i = 0; i < 16; i++) {
                int m = half * 16 + i;
                float sx = __shfl_sync(0xffffffffu, rx, m);
                float sy = __shfl_sync(0xffffffffu, ry, m);
                acc = fmaf(sx, decW[(2 * m) * 16 + o], acc);
                acc = fmaf(sy, decW[(2 * m + 1) * 16 + o], acc);
            }
            acc += __shfl_down_sync(0xffffffffu, acc, 16);
            if (half == 0) out[node * 16 + o] = acc;
        }
    }
}

// ---------------- the single persistent kernel ----------------
__global__ void __launch_bounds__(TPB, BLK_PER_SM) k_mega(
    const float* __restrict__ x, const int* __restrict__ ei,
    const float* __restrict__ ew, const float* __restrict__ encW,
    const float* __restrict__ encb, const float* __restrict__ cayB,
    const float* __restrict__ decW, float* __restrict__ out)
{
    __shared__ SmemU su;
    __shared__ double red[WPB][5];
    __shared__ float sa[5];

    const int* src = ei;
    const int* dst = ei + N_EDGES;
    int gtid = blockIdx.x * TPB + threadIdx.x;

    // Phase 1: one-pass padded-row scatter (g_cur pre-zeroed) || encoder || zero GGbuf[0]
    for (int e = gtid; e < N_EDGES; e += NTHREADS) {
        int d = dst[e];
        int pos = atomicAdd(&g_cur[d], 1);
        g_edge[d * PAD + pos] = make_int2(src[e], __float_as_int(ew[e]));
    }
    if (gtid < 15) g_GGbuf[0][gtid] = 0.0;
    encode_phase(x, encW, encb, &su);
    gbar();

    // Phase 2: count-prefix scan for partition (block 0, g_cur preserved) || Cayley (block 1)
    if (blockIdx.x == 0) {
        int t = threadIdx.x;
        const int CH = (N_NODES + TPB - 1) / TPB;   // 20
        int beg = t * CH, end = beg + CH; if (end > N_NODES) end = N_NODES;
        int s = 0;
        for (int i = beg; i < end; i++) s += g_cur[i];
        su.part[t] = s;
        __syncthreads();
        for (int d = 1; d < TPB; d <<= 1) {
            int v = (t >= d) ? su.part[t - d] : 0;
            __syncthreads();
            su.part[t] += v;
            __syncthreads();
        }
        int off = (t > 0) ? su.part[t - 1] : 0;
        for (int i = beg; i < end; i++) {
            g_rowptr[i] = off;
            off += g_cur[i];
        }
        if (t == 0) g_rowptr[N_NODES] = N_EDGES;
    } else if (blockIdx.x == 1) {
        theta_phase(cayB, &su);
    }
    gbar();

    // Phase 3: balanced warp partition (binary search on cost prefix) || stage packed Theta
    if (gtid <= NWARPS) {
        if (gtid == NWARPS) {
            g_wstart[NWARPS] = N_NODES;
        } else {
            long long target = (long long)gtid * COST_TOTAL / NWARPS;
            int lo = 0, hi = N_NODES;
            while (lo < hi) {
                int mid = (lo + hi) >> 1;
                long long c = (long long)g_rowptr[mid] + (long long)NODE_COST * mid;
                if (c < target) lo = mid + 1; else hi = mid;
            }
            g_wstart[gtid] = lo;
        }
    }
    for (int i = threadIdx.x; i < 1024; i += TPB) {
        int m = i >> 5, l = i & 31;
        float a0 = g_ThT[(2 * m) * 64 + 2 * l];
        float a1 = g_ThT[(2 * m + 1) * 64 + 2 * l];
        float b0 = g_ThT[(2 * m) * 64 + 2 * l + 1];
        float b1 = g_ThT[(2 * m + 1) * 64 + 2 * l + 1];
        su.mix.T[m][l] = make_ulonglong2(pack2(make_float2(a0, a1)),
                                         pack2(make_float2(b0, b1)));
    }
    gbar();

    // history: 5 PR sweeps (w ping-pong); uu read from b / F[i-1]
    for (int i = 0; i < AAM; i++) {
        spmm_phase(i, i + 1, &g_GGbuf[0][i * (i + 1) / 2], (i < AAM - 1) ? 1 : 0, 1,
                   g_wbuf[i & 1], (i == 0) ? g_b : g_F[i - 1], g_wbuf[(i + 1) & 1],
                   &su, red);
        gbar();
    }

    // Anderson: combine -> spmm (last g() dead); final combine fuses decode.
    for (int k = 0; k < AAM; k++) {
        combine_phase(k, sa, decW, out);
        if (k < AAM - 1) {
            gbar();
            spmm_phase(k, 5, g_GGrow[k & 1], 0, (k < AAM - 2) ? 1 : 0,
                       g_wbuf[0], g_u, 0, &su, red);
            gbar();
        }
    }

    // tail: re-zero g_cur for the NEXT launch (last reader was spmm(k=3), behind a gbar)
    for (int i = gtid; i < N_NODES; i += NTHREADS) g_cur[i] = 0;
}

// ---------------- launch: ONE kernel ----------------
extern "C" void kernel_launch(void* const* d_in, const int* in_sizes, int n_in,
                              void* d_out, int out_size) {
    const float* x    = (const float*)d_in[0];
    const int*   ei   = (const int*)  d_in[1];
    const float* ew   = (const float*)d_in[2];
    const float* encW = (const float*)d_in[3];
    const float* encb = (const float*)d_in[4];
    const float* cayB = (const float*)d_in[5];
    const float* decW = (const float*)d_in[6];
    float* out = (float*)d_out;

    k_mega<<<GRID_BLOCKS, TPB>>>(x, ei, ew, encW, encb, cayB, decW, out);
}

// round 13
// speedup vs baseline: 1.1485x; 1.0151x over previous
#include <cuda_runtime.h>
#include <cuda_fp16.h>

#define N_NODES 10000
#define N_EDGES 320000
#define D_IN    128
#define D_HID   64
#define D_OUT   16
#define NH      (N_NODES * D_HID)
#define AAM     5
#define PAD     128                  // padded edge-row length
#define TPB         512
#define BLK_PER_SM  2
#define GRID_BLOCKS 296              // 148 SMs x 2 blocks guaranteed resident
#define WPB         (TPB / 32)       // 16
#define NWARPS      (GRID_BLOCKS * WPB)          // 4736
#define NTHREADS    (GRID_BLOCKS * TPB)
#define NODE_COST   48
#define COST_TOTAL  (N_EDGES + NODE_COST * N_NODES)

typedef unsigned long long ull;

// ---------------- device scratch ----------------
__device__ float  g_b[NH];
__device__ float  g_u[NH];                  // written only by Anderson combines
__device__ __half g_wbuf[2][NH];            // fp16 SPMM input (only gather reads it)
__device__ float  g_F[AAM][NH];
__device__ float  g_G[AAM][NH];
__device__ float  g_ThT[D_HID * D_HID];     // ThT[k*64+c] = Theta[c][k]
__device__ int    g_rowptr[N_NODES + 1];    // prefix of counts (partition only)
__device__ int    g_cur[N_NODES];           // zero at launch entry (re-zeroed at kernel tail)
__device__ __align__(16) int2 g_edge[N_NODES * PAD];   // padded edge rows
__device__ int    g_wstart[NWARPS + 1];
__device__ double g_GGbuf[2][15];
__device__ double g_GGrow[2][5];
__device__ unsigned          g_bar_cnt;
__device__ volatile unsigned g_bar_gen;

union SmemU {
    struct { float M[64][128]; float fct[64]; } th;            // 33 KB (setup)
    struct {
        ulonglong2 T[32][32];     // 16KB: {A[m][l], B[m][l]} packed Theta
        ulonglong2 s[WPB][32];    // 8KB: per-warp staged (sA, sB) / encoder x rows
    } mix;                        // 24 KB
    int part[TPB];
};

// ---------------- f32x2 helpers ----------------
__device__ __forceinline__ void fma2(ull& d, ull a, ull b) {
    asm("fma.rn.f32x2 %0, %1, %2, %0;" : "+l"(d) : "l"(a), "l"(b));
}
__device__ __forceinline__ ull pack2(float2 v) {
    ull r; asm("mov.b64 %0, {%1, %2};" : "=l"(r) : "f"(v.x), "f"(v.y)); return r;
}
__device__ __forceinline__ float2 unpack2(ull v) {
    float2 r; asm("mov.b64 {%0, %1}, %2;" : "=f"(r.x), "=f"(r.y) : "l"(v)); return r;
}
__device__ __forceinline__ float2 gfma(float2 a, float w, float2 v) {
    a.x = fmaf(w, v.x, a.x); a.y = fmaf(w, v.y, a.y); return a;
}

// ---------------- software grid barrier ----------------
__device__ __forceinline__ void gbar() {
    __syncthreads();
    if (threadIdx.x == 0) {
        __threadfence();
        unsigned gen = g_bar_gen;
        if (atomicAdd(&g_bar_cnt, 1u) == GRID_BLOCKS - 1u) {
            g_bar_cnt = 0u;
            __threadfence();
            g_bar_gen = gen + 1u;
        } else {
            while (g_bar_gen == gen) { __nanosleep(32); }
        }
        __threadfence();
    }
    __syncthreads();
}

// ---------------- Cayley: Theta = (I+Om)^-1 (I-Om) ----------------
__device__ void theta_phase(const float* __restrict__ B, SmemU* su) {
    int tid = threadIdx.x;
    for (int idx = tid; idx < 64 * 64; idx += TPB) {
        int i = idx >> 6, j = idx & 63;
        float om = 0.5f * (B[i * 64 + j] - B[j * 64 + i]);
        float e  = (i == j) ? 1.f : 0.f;
        su->th.M[i][j]      = e + om;
        su->th.M[i][64 + j] = e - om;
    }
    __syncthreads();
    for (int k = 0; k < 64; k++) {
        float inv = 1.f / su->th.M[k][k];
        __syncthreads();
        for (int j = tid; j < 128; j += TPB) su->th.M[k][j] *= inv;
        __syncthreads();
        for (int r = tid; r < 64; r += TPB) su->th.fct[r] = su->th.M[r][k];
        __syncthreads();
        for (int idx = tid; idx < 64 * 128; idx += TPB) {
            int r = idx >> 7, j = idx & 127;
            if (r != k) su->th.M[r][j] -= su->th.fct[r] * su->th.M[k][j];
        }
        __syncthreads();
    }
    for (int idx = tid; idx < 64 * 64; idx += TPB) {
        int k = idx >> 6, c = idx & 63;
        g_ThT[idx] = su->th.M[c][64 + k];
    }
}

// ---------------- encoder + b/w0 (x staged through smem, coalesced) ----------------
__device__ void encode_phase(const float* __restrict__ x, const float* __restrict__ W,
                             const float* __restrict__ bias, SmemU* su) {
    int warp = threadIdx.x >> 5, cp = threadIdx.x & 31;
    int g = blockIdx.x * WPB + warp;
    const float2* __restrict__ W2 = (const float2*)W;
    float4* sx = (float4*)&su->mix.s[warp][0];   // 512B = one x row
    float2 bsv = ((const float2*)bias)[cp];
    for (int node = g; node < N_NODES; node += NWARPS) {
        sx[cp] = ((const float4*)(x + node * D_IN))[cp];
        __syncwarp();
        const float* xs = (const float*)sx;
        float2 acc = bsv;
#pragma unroll 16
        for (int k = 0; k < D_IN; k++) {
            float  xk = xs[k];
            float2 w2 = W2[k * 32 + cp];
            acc.x = fmaf(xk, w2.x, acc.x);
            acc.y = fmaf(xk, w2.y, acc.y);
        }
        __syncwarp();
        int row = node * 32 + cp;
        ((float2*)g_b)[row] = acc;
        ((__half2*)g_wbuf[0])[row] =
            __floats2half2_rn(2.f * fmaxf(acc.x, 0.f), 2.f * fmaxf(acc.y, 0.f));
    }
}

// ---------------- interleaved dual-node gather (fp16 values, int4 descriptors) ----------------
__device__ __forceinline__ void gather2(const int2* __restrict__ eg,
                                        const __half2* __restrict__ wv,
                                        int bA, int cA, int bB, int cB,
                                        int lane, float2& outA, float2& outB) {
    const int4* __restrict__ e4A = (const int4*)(eg + bA);
    const int4* __restrict__ e4B = (const int4*)(eg + bB);
    float2 aA0 = {0.f, 0.f}, aA1 = {0.f, 0.f};
    float2 aB0 = {0.f, 0.f}, aB1 = {0.f, 0.f};
    int hA = 0, heA = cA >> 1;
    int hB = 0, heB = cB >> 1;
    while (hA + 2 <= heA && hB + 2 <= heB) {
        int4 dA0 = e4A[hA], dA1 = e4A[hA + 1];
        int4 dB0 = e4B[hB], dB1 = e4B[hB + 1];
        __half2 vA0 = wv[dA0.x * 32 + lane], vA1 = wv[dA0.z * 32 + lane];
        __half2 vA2 = wv[dA1.x * 32 + lane], vA3 = wv[dA1.z * 32 + lane];
        __half2 vB0 = wv[dB0.x * 32 + lane], vB1 = wv[dB0.z * 32 + lane];
        __half2 vB2 = wv[dB1.x * 32 + lane], vB3 = wv[dB1.z * 32 + lane];
        aA0 = gfma(aA0, __int_as_float(dA0.y), __half22float2(vA0));
        aA1 = gfma(aA1, __int_as_float(dA0.w), __half22float2(vA1));
        aA0 = gfma(aA0, __int_as_float(dA1.y), __half22float2(vA2));
        aA1 = gfma(aA1, __int_as_float(dA1.w), __half22float2(vA3));
        aB0 = gfma(aB0, __int_as_float(dB0.y), __half22float2(vB0));
        aB1 = gfma(aB1, __int_as_float(dB0.w), __half22float2(vB1));
        aB0 = gfma(aB0, __int_as_float(dB1.y), __half22float2(vB2));
        aB1 = gfma(aB1, __int_as_float(dB1.w), __half22float2(vB3));
        hA += 2; hB += 2;
    }
    for (; hA < heA; ++hA) {
        int4 d = e4A[hA];
        aA0 = gfma(aA0, __int_as_float(d.y), __half22float2(wv[d.x * 32 + lane]));
        aA1 = gfma(aA1, __int_as_float(d.w), __half22float2(wv[d.z * 32 + lane]));
    }
    if (cA & 1) {
        int2 d = eg[bA + cA - 1];
        aA0 = gfma(aA0, __int_as_float(d.y), __half22float2(wv[d.x * 32 + lane]));
    }
    for (; hB < heB; ++hB) {
        int4 d = e4B[hB];
        aB0 = gfma(aB0, __int_as_float(d.y), __half22float2(wv[d.x * 32 + lane]));
        aB1 = gfma(aB1, __int_as_float(d.w), __half22float2(wv[d.z * 32 + lane]));
    }
    if (cB & 1) {
        int2 d = eg[bB + cB - 1];
        aB0 = gfma(aB0, __int_as_float(d.y), __half22float2(wv[d.x * 32 + lane]));
    }
    outA = make_float2(aA0.x + aA1.x, aA0.y + aA1.y);
    outB = make_float2(aB0.x + aB1.x, aB0.y + aB1.y);
}

// ---------------- per-node epilogue ----------------
__device__ __forceinline__ void epilogue(int node, int lane, float2 mix, int slot,
                                         int npairs, int wr_next, int wr_g,
                                         const float* __restrict__ usrc,
                                         __half* __restrict__ wdst, float* p) {
    int row = node * 32 + lane;
    float2 bb = ((const float2*)g_b)[row];
    float2 uu = ((const float2*)usrc)[row];
    float2 val = make_float2(bb.x + 0.5f * mix.x, bb.y + 0.5f * mix.y);
    ((float2*)g_F[slot])[row] = val;
    float2 gn = make_float2(val.x - uu.x, val.y - uu.y);
    if (wr_g) ((float2*)g_G[slot])[row] = gn;
    if (wr_next) {
        ((__half2*)wdst)[row] =
            __floats2half2_rn(2.f * fmaxf(val.x, 0.f) - val.x + bb.x,
                              2.f * fmaxf(val.y, 0.f) - val.y + bb.y);
    }
    for (int j = 0; j < npairs; ++j) {
        float2 gj = (j == slot) ? gn : ((const float2*)g_G[j])[row];
        p[j] = fmaf(gn.x, gj.x, fmaf(gn.y, gj.y, p[j]));
    }
}

// ---------------- fused SPMM + LDS.128 mix + G + Gram partials ----------------
__device__ void spmm_phase(int slot, int npairs, double* target, int wr_next, int wr_g,
                           const __half* __restrict__ wsrc,
                           const float* __restrict__ usrc,
                           __half* __restrict__ wdst,
                           SmemU* su, double (*red)[5]) {
    int warp = threadIdx.x >> 5, lane = threadIdx.x & 31;
    int w = blockIdx.x * WPB + warp;
    const int2*    __restrict__ eg = g_edge;
    const __half2* __restrict__ wv = (const __half2*)wsrc;
    float p[5];
#pragma unroll
    for (int j = 0; j < 5; j++) p[j] = 0.f;

    int n = g_wstart[w], ne = g_wstart[w + 1];

    for (; n + 1 < ne; n += 2) {
        int cA = g_cur[n], cB = g_cur[n + 1];
        float2 accA, accB;
        gather2(eg, wv, n * PAD, cA, (n + 1) * PAD, cB, lane, accA, accB);

        __syncwarp();
        su->mix.s[warp][lane] = make_ulonglong2(pack2(accA), pack2(accB));
        __syncwarp();

        ull PA = 0ull, QA = 0ull, PB = 0ull, QB = 0ull;
#pragma unroll
        for (int m = 0; m < 32; ++m) {
            ulonglong2 sp = su->mix.s[warp][m];   // broadcast LDS.128
            ulonglong2 T  = su->mix.T[m][lane];   // conflict-free LDS.128
            fma2(PA, T.x, sp.x); fma2(QA, T.y, sp.x);
            fma2(PB, T.x, sp.y); fma2(QB, T.y, sp.y);
        }
        float2 pA = unpack2(PA), qA = unpack2(QA);
        float2 pB = unpack2(PB), qB = unpack2(QB);
        epilogue(n,     lane, make_float2(pA.x + pA.y, qA.x + qA.y),
                 slot, npairs, wr_next, wr_g, usrc, wdst, p);
        epilogue(n + 1, lane, make_float2(pB.x + pB.y, qB.x + qB.y),
                 slot, npairs, wr_next, wr_g, usrc, wdst, p);
    }
    if (n < ne) {
        int cA = g_cur[n];
        float2 acc, dummy;
        gather2(eg, wv, n * PAD, cA, n * PAD, 0, lane, acc, dummy);
        __syncwarp();
        su->mix.s[warp][lane] = make_ulonglong2(pack2(acc), 0ull);
        __syncwarp();
        ull PA = 0ull, QA = 0ull;
#pragma unroll
        for (int m = 0; m < 32; ++m) {
            ulonglong2 sp = su->mix.s[warp][m];
            ulonglong2 T  = su->mix.T[m][lane];
            fma2(PA, T.x, sp.x);
            fma2(QA, T.y, sp.x);
        }
        float2 pA = unpack2(PA), qA = unpack2(QA);
        epilogue(n, lane, make_float2(pA.x + pA.y, qA.x + qA.y),
                 slot, npairs, wr_next, wr_g, usrc, wdst, p);
    }

#pragma unroll
    for (int j = 0; j < 5; ++j)
        for (int off = 16; off > 0; off >>= 1)
            p[j] += __shfl_down_sync(0xffffffffu, p[j], off);
    __syncthreads();
    if (lane == 0)
        for (int j = 0; j < 5; ++j) red[warp][j] = (double)p[j];
    __syncthreads();
    if (threadIdx.x < npairs) {
        int j = threadIdx.x;
        double s = 0.0;
        for (int ww = 0; ww < WPB; ww++) s += red[ww][j];
        atomicAdd(&target[j], s);
    }
}

// ---------------- combine(k): Gram merge + 5x5 solve + u_new (+ fused decode at k=4) ----------------
__device__ void combine_phase(int k, float* sa, const float* __restrict__ decW,
                              float* __restrict__ out) {
    if (threadIdx.x == 0) {
        double M[5][5];
        const double* base = g_GGbuf[k & 1];
        int c = 0;
        for (int i = 0; i < 5; i++)
            for (int j = 0; j <= i; j++) { M[i][j] = base[c]; M[j][i] = base[c]; c++; }
        if (k > 0) {
            int idx = k - 1;
            const double* row = g_GGrow[(k - 1) & 1];
            for (int j = 0; j < 5; j++) { M[idx][j] = row[j]; M[j][idx] = row[j]; }
        }
        if (blockIdx.x == 0 && k < AAM - 1) {
            c = 0;
            for (int i = 0; i < 5; i++)
                for (int j = 0; j <= i; j++) g_GGbuf[(k + 1) & 1][c++] = M[i][j];
            for (int j = 0; j < 5; j++) g_GGrow[k & 1][j] = 0.0;
        }
        float A[5][6];
        for (int i = 0; i < 5; i++) {
            for (int j = 0; j < 5; j++) A[i][j] = (float)M[i][j];
            A[i][i] += 1e-4f;
            A[i][5] = 1.f;
        }
        for (int kk = 0; kk < 5; kk++) {
            int piv = kk; float mx = fabsf(A[kk][kk]);
            for (int r = kk + 1; r < 5; r++)
                if (fabsf(A[r][kk]) > mx) { mx = fabsf(A[r][kk]); piv = r; }
            if (piv != kk)
                for (int j = 0; j < 6; j++) { float t = A[kk][j]; A[kk][j] = A[piv][j]; A[piv][j] = t; }
            float inv = 1.f / A[kk][kk];
            for (int r = kk + 1; r < 5; r++) {
                float f = A[r][kk] * inv;
                for (int j = kk; j < 6; j++) A[r][j] -= f * A[kk][j];
            }
        }
        float a[5];
        for (int kk = 4; kk >= 0; kk--) {
            float s = A[kk][5];
            for (int j = kk + 1; j < 5; j++) s -= A[kk][j] * a[j];
            a[kk] = s / A[kk][kk];
        }
        float sum = a[0] + a[1] + a[2] + a[3] + a[4];
        for (int j = 0; j < 5; j++) sa[j] = a[j] / sum;
    }
    __syncthreads();
    float a0 = sa[0], a1 = sa[1], a2 = sa[2], a3 = sa[3], a4 = sa[4];

    int warp = threadIdx.x >> 5, lane = threadIdx.x & 31;
    int g = blockIdx.x * WPB + warp;
    const float2* F0 = (const float2*)g_F[0];
    const float2* F1 = (const float2*)g_F[1];
    const float2* F2 = (const float2*)g_F[2];
    const float2* F3 = (const float2*)g_F[3];
    const float2* F4 = (const float2*)g_F[4];
    for (int node = g; node < N_NODES; node += NWARPS) {
        int idx = node * 32 + lane;
        float2 f0 = F0[idx], f1 = F1[idx], f2 = F2[idx], f3 = F3[idx], f4 = F4[idx];
        float2 un;
        un.x = a0 * f0.x + a1 * f1.x + a2 * f2.x + a3 * f3.x + a4 * f4.x;
        un.y = a0 * f0.y + a1 * f1.y + a2 * f2.y + a3 * f3.y + a4 * f4.y;
        if (k < AAM - 1) {
            ((float2*)g_u)[idx] = un;
            float2 bb = ((const float2*)g_b)[idx];
            ((__half2*)g_wbuf[0])[idx] =
                __floats2half2_rn(2.f * fmaxf(un.x, 0.f) - un.x + bb.x,
                                  2.f * fmaxf(un.y, 0.f) - un.y + bb.y);
        } else {
            float rx = fmaxf(un.x, 0.f), ry = fmaxf(un.y, 0.f);
            int o = lane & 15, half = lane >> 4;
            float acc = 0.f;
#pragma unroll
            for (int i = 0; i < 16; i++) {
                int m = half * 16 + i;
                float sx = __shfl_sync(0xffffffffu, rx, m);
                float sy = __shfl_sync(0xffffffffu, ry, m);
                acc = fmaf(sx, decW[(2 * m) * 16 + o], acc);
                acc = fmaf(sy, decW[(2 * m + 1) * 16 + o], acc);
            }
            acc += __shfl_down_sync(0xffffffffu, acc, 16);
            if (half == 0) out[node * 16 + o] = acc;
        }
    }
}

// ---------------- the single persistent kernel ----------------
__global__ void __launch_bounds__(TPB, BLK_PER_SM) k_mega(
    const float* __restrict__ x, const int* __restrict__ ei,
    const float* __restrict__ ew, const float* __restrict__ encW,
    const float* __restrict__ encb, const float* __restrict__ cayB,
    const float* __restrict__ decW, float* __restrict__ out)
{
    __shared__ SmemU su;
    __shared__ double red[WPB][5];
    __shared__ float sa[5];

    const int* src = ei;
    const int* dst = ei + N_EDGES;
    int gtid = blockIdx.x * TPB + threadIdx.x;

    // Phase 1: one-pass padded-row scatter (g_cur pre-zeroed) || encoder || zero GGbuf[0]
    for (int e = gtid; e < N_EDGES; e += NTHREADS) {
        int d = dst[e];
        int pos = atomicAdd(&g_cur[d], 1);
        g_edge[d * PAD + pos] = make_int2(src[e], __float_as_int(ew[e]));
    }
    if (gtid < 15) g_GGbuf[0][gtid] = 0.0;
    encode_phase(x, encW, encb, &su);
    gbar();

    // Phase 2: count-prefix scan (block 0) || Cayley theta (block 1)
    if (blockIdx.x == 0) {
        int t = threadIdx.x;
        const int CH = (N_NODES + TPB - 1) / TPB;   // 20
        int beg = t * CH, end = beg + CH; if (end > N_NODES) end = N_NODES;
        int s = 0;
        for (int i = beg; i < end; i++) s += g_cur[i];
        su.part[t] = s;
        __syncthreads();
        for (int d = 1; d < TPB; d <<= 1) {
            int v = (t >= d) ? su.part[t - d] : 0;
            __syncthreads();
            su.part[t] += v;
            __syncthreads();
        }
        int off = (t > 0) ? su.part[t - 1] : 0;
        for (int i = beg; i < end; i++) {
            g_rowptr[i] = off;
            off += g_cur[i];
        }
        if (t == 0) g_rowptr[N_NODES] = N_EDGES;
    } else if (blockIdx.x == 1) {
        theta_phase(cayB, &su);
    }
    gbar();

    // Phase 3: balanced warp partition || stage packed Theta
    if (gtid <= NWARPS) {
        if (gtid == NWARPS) {
            g_wstart[NWARPS] = N_NODES;
        } else {
            long long target = (long long)gtid * COST_TOTAL / NWARPS;
            int lo = 0, hi = N_NODES;
            while (lo < hi) {
                int mid = (lo + hi) >> 1;
                long long c = (long long)g_rowptr[mid] + (long long)NODE_COST * mid;
                if (c < target) lo = mid + 1; else hi = mid;
            }
            g_wstart[gtid] = lo;
        }
    }
    for (int i = threadIdx.x; i < 1024; i += TPB) {
        int m = i >> 5, l = i & 31;
        float a0 = g_ThT[(2 * m) * 64 + 2 * l];
        float a1 = g_ThT[(2 * m + 1) * 64 + 2 * l];
        float b0 = g_ThT[(2 * m) * 64 + 2 * l + 1];
        float b1 = g_ThT[(2 * m + 1) * 64 + 2 * l + 1];
        su.mix.T[m][l] = make_ulonglong2(pack2(make_float2(a0, a1)),
                                         pack2(make_float2(b0, b1)));
    }
    gbar();

    // history: 5 PR sweeps (w ping-pong); uu read from b / F[i-1]
    for (int i = 0; i < AAM; i++) {
        spmm_phase(i, i + 1, &g_GGbuf[0][i * (i + 1) / 2], (i < AAM - 1) ? 1 : 0, 1,
                   g_wbuf[i & 1], (i == 0) ? g_b : g_F[i - 1], g_wbuf[(i + 1) & 1],
                   &su, red);
        gbar();
    }

    // Anderson: combine -> spmm (last g() dead); final combine fuses decode.
    for (int k = 0; k < AAM; k++) {
        combine_phase(k, sa, decW, out);
        if (k < AAM - 1) {
            gbar();
            spmm_phase(k, 5, g_GGrow[k & 1], 0, (k < AAM - 2) ? 1 : 0,
                       g_wbuf[0], g_u, 0, &su, red);
            gbar();
        }
    }

    // tail: re-zero g_cur for the NEXT launch (last reader was spmm(k=3), behind a gbar)
    for (int i = gtid; i < N_NODES; i += NTHREADS) g_cur[i] = 0;
}

// ---------------- launch: ONE kernel ----------------
extern "C" void kernel_launch(void* const* d_in, const int* in_sizes, int n_in,
                              void* d_out, int out_size) {
    const float* x    = (const float*)d_in[0];
    const int*   ei   = (const int*)  d_in[1];
    const float* ew   = (const float*)d_in[2];
    const float* encW = (const float*)d_in[3];
    const float* encb = (const float*)d_in[4];
    const float* cayB = (const float*)d_in[5];
    const float* decW = (const float*)d_in[6];
    float* out = (float*)d_out;

    k_mega<<<GRID_BLOCKS, TPB>>>(x, ei, ew, encW, encb, cayB, decW, out);
}

// round 14
// speedup vs baseline: 1.1688x; 1.0177x over previous
#include <cuda_runtime.h>
#include <cuda_fp16.h>

#define N_NODES 10000
#define N_EDGES 320000
#define D_IN    128
#define D_HID   64
#define D_OUT   16
#define NH      (N_NODES * D_HID)
#define AAM     5
#define PAD     128                  // padded edge-row length
#define TPB         512
#define BLK_PER_SM  2
#define GRID_BLOCKS 296              // 148 SMs x 2 blocks guaranteed resident
#define WPB         (TPB / 32)       // 16
#define NWARPS      (GRID_BLOCKS * WPB)          // 4736
#define NTHREADS    (GRID_BLOCKS * TPB)
#define NODE_COST   48
#define COST_TOTAL  (N_EDGES + NODE_COST * N_NODES)

typedef unsigned long long ull;

// ---------------- device scratch ----------------
__device__ float  g_b[NH];
__device__ float  g_u[NH];                  // written only by Anderson combines
__device__ __half g_wbuf[2][NH];            // fp16 SPMM input (only gather reads it)
__device__ float  g_F[AAM][NH];
__device__ float  g_G[AAM][NH];
__device__ float  g_ThT[D_HID * D_HID];     // ThT[k*64+c] = Theta[c][k]
__device__ int    g_rowptr[N_NODES + 1];    // prefix of counts (partition only)
__device__ int    g_cur[N_NODES];           // zero at launch entry (re-zeroed at kernel tail)
__device__ __align__(16) int2 g_edge[N_NODES * PAD];   // padded edge rows
__device__ int    g_wstart[NWARPS + 1];
__device__ double g_GGbuf[2][15];
__device__ double g_GGrow[2][5];
__device__ unsigned          g_bar_cnt;
__device__ volatile unsigned g_bar_gen;

union SmemU {
    struct { float M[64][128]; float fct[64]; } th;            // 33 KB (setup)
    struct {
        ulonglong2 T[32][32];     // 16KB: {A[m][l], B[m][l]} packed Theta
        ulonglong2 s[WPB][32];    // 8KB: per-warp staged (sA, sB) / encoder x rows
    } mix;                        // 24 KB
    int part[TPB];
};

// ---------------- f32x2 helpers ----------------
__device__ __forceinline__ void fma2(ull& d, ull a, ull b) {
    asm("fma.rn.f32x2 %0, %1, %2, %0;" : "+l"(d) : "l"(a), "l"(b));
}
__device__ __forceinline__ ull pack2(float2 v) {
    ull r; asm("mov.b64 %0, {%1, %2};" : "=l"(r) : "f"(v.x), "f"(v.y)); return r;
}
__device__ __forceinline__ float2 unpack2(ull v) {
    float2 r; asm("mov.b64 {%0, %1}, %2;" : "=f"(r.x), "=f"(r.y) : "l"(v)); return r;
}
__device__ __forceinline__ float2 gfma(float2 a, float w, float2 v) {
    a.x = fmaf(w, v.x, a.x); a.y = fmaf(w, v.y, a.y); return a;
}

// ---------------- software grid barrier ----------------
__device__ __forceinline__ void gbar() {
    __syncthreads();
    if (threadIdx.x == 0) {
        __threadfence();
        unsigned gen = g_bar_gen;
        if (atomicAdd(&g_bar_cnt, 1u) == GRID_BLOCKS - 1u) {
            g_bar_cnt = 0u;
            __threadfence();
            g_bar_gen = gen + 1u;
        } else {
            while (g_bar_gen == gen) { __nanosleep(32); }
        }
        __threadfence();
    }
    __syncthreads();
}

// ---------------- Cayley: Theta = (I+Om)^-1 (I-Om) ----------------
__device__ void theta_phase(const float* __restrict__ B, SmemU* su) {
    int tid = threadIdx.x;
    for (int idx = tid; idx < 64 * 64; idx += TPB) {
        int i = idx >> 6, j = idx & 63;
        float om = 0.5f * (B[i * 64 + j] - B[j * 64 + i]);
        float e  = (i == j) ? 1.f : 0.f;
        su->th.M[i][j]      = e + om;
        su->th.M[i][64 + j] = e - om;
    }
    __syncthreads();
    for (int k = 0; k < 64; k++) {
        float inv = 1.f / su->th.M[k][k];
        __syncthreads();
        for (int j = tid; j < 128; j += TPB) su->th.M[k][j] *= inv;
        __syncthreads();
        for (int r = tid; r < 64; r += TPB) su->th.fct[r] = su->th.M[r][k];
        __syncthreads();
        for (int idx = tid; idx < 64 * 128; idx += TPB) {
            int r = idx >> 7, j = idx & 127;
            if (r != k) su->th.M[r][j] -= su->th.fct[r] * su->th.M[k][j];
        }
        __syncthreads();
    }
    for (int idx = tid; idx < 64 * 64; idx += TPB) {
        int k = idx >> 6, c = idx & 63;
        g_ThT[idx] = su->th.M[c][64 + k];
    }
}

// ---------------- encoder + b/w0 (x staged through smem, coalesced) ----------------
__device__ void encode_phase(const float* __restrict__ x, const float* __restrict__ W,
                             const float* __restrict__ bias, SmemU* su) {
    int warp = threadIdx.x >> 5, cp = threadIdx.x & 31;
    int g = blockIdx.x * WPB + warp;
    const float2* __restrict__ W2 = (const float2*)W;
    float4* sx = (float4*)&su->mix.s[warp][0];   // 512B = one x row
    float2 bsv = ((const float2*)bias)[cp];
    for (int node = g; node < N_NODES; node += NWARPS) {
        sx[cp] = ((const float4*)(x + node * D_IN))[cp];
        __syncwarp();
        const float* xs = (const float*)sx;
        float2 acc = bsv;
#pragma unroll 16
        for (int k = 0; k < D_IN; k++) {
            float  xk = xs[k];
            float2 w2 = W2[k * 32 + cp];
            acc.x = fmaf(xk, w2.x, acc.x);
            acc.y = fmaf(xk, w2.y, acc.y);
        }
        __syncwarp();
        int row = node * 32 + cp;
        ((float2*)g_b)[row] = acc;
        ((__half2*)g_wbuf[0])[row] =
            __floats2half2_rn(2.f * fmaxf(acc.x, 0.f), 2.f * fmaxf(acc.y, 0.f));
    }
}

// ---------------- branch-free interleaved dual-node gather (counts pre-rounded to 4) ----
__device__ __forceinline__ void gather2(const int2* __restrict__ eg,
                                        const __half2* __restrict__ wv,
                                        int bA, int hcA, int bB, int hcB,
                                        int lane, float2& outA, float2& outB) {
    const int4* __restrict__ e4A = (const int4*)(eg + bA);
    const int4* __restrict__ e4B = (const int4*)(eg + bB);
    float2 aA0 = {0.f, 0.f}, aA1 = {0.f, 0.f};
    float2 aB0 = {0.f, 0.f}, aB1 = {0.f, 0.f};
    int hA = 0, hB = 0;
    // main interleaved loop: 8 edges (4+4) per iteration, no conditionals inside
    while (hA + 2 <= hcA && hB + 2 <= hcB) {
        int4 dA0 = e4A[hA], dA1 = e4A[hA + 1];
        int4 dB0 = e4B[hB], dB1 = e4B[hB + 1];
        __half2 vA0 = wv[dA0.x * 32 + lane], vA1 = wv[dA0.z * 32 + lane];
        __half2 vA2 = wv[dA1.x * 32 + lane], vA3 = wv[dA1.z * 32 + lane];
        __half2 vB0 = wv[dB0.x * 32 + lane], vB1 = wv[dB0.z * 32 + lane];
        __half2 vB2 = wv[dB1.x * 32 + lane], vB3 = wv[dB1.z * 32 + lane];
        aA0 = gfma(aA0, __int_as_float(dA0.y), __half22float2(vA0));
        aA1 = gfma(aA1, __int_as_float(dA0.w), __half22float2(vA1));
        aA0 = gfma(aA0, __int_as_float(dA1.y), __half22float2(vA2));
        aA1 = gfma(aA1, __int_as_float(dA1.w), __half22float2(vA3));
        aB0 = gfma(aB0, __int_as_float(dB0.y), __half22float2(vB0));
        aB1 = gfma(aB1, __int_as_float(dB0.w), __half22float2(vB1));
        aB0 = gfma(aB0, __int_as_float(dB1.y), __half22float2(vB2));
        aB1 = gfma(aB1, __int_as_float(dB1.w), __half22float2(vB3));
        hA += 2; hB += 2;
    }
    // clean remainder loops (counts are multiples of 2 int4-units? multiples of 2)
    for (; hA + 2 <= hcA; hA += 2) {
        int4 d0 = e4A[hA], d1 = e4A[hA + 1];
        __half2 v0 = wv[d0.x * 32 + lane], v1 = wv[d0.z * 32 + lane];
        __half2 v2 = wv[d1.x * 32 + lane], v3 = wv[d1.z * 32 + lane];
        aA0 = gfma(aA0, __int_as_float(d0.y), __half22float2(v0));
        aA1 = gfma(aA1, __int_as_float(d0.w), __half22float2(v1));
        aA0 = gfma(aA0, __int_as_float(d1.y), __half22float2(v2));
        aA1 = gfma(aA1, __int_as_float(d1.w), __half22float2(v3));
    }
    for (; hB + 2 <= hcB; hB += 2) {
        int4 d0 = e4B[hB], d1 = e4B[hB + 1];
        __half2 v0 = wv[d0.x * 32 + lane], v1 = wv[d0.z * 32 + lane];
        __half2 v2 = wv[d1.x * 32 + lane], v3 = wv[d1.z * 32 + lane];
        aB0 = gfma(aB0, __int_as_float(d0.y), __half22float2(v0));
        aB1 = gfma(aB1, __int_as_float(d0.w), __half22float2(v1));
        aB0 = gfma(aB0, __int_as_float(d1.y), __half22float2(v2));
        aB1 = gfma(aB1, __int_as_float(d1.w), __half22float2(v3));
    }
    outA = make_float2(aA0.x + aA1.x, aA0.y + aA1.y);
    outB = make_float2(aB0.x + aB1.x, aB0.y + aB1.y);
}

// ---------------- per-node epilogue ----------------
__device__ __forceinline__ void epilogue(int node, int lane, float2 mix, int slot,
                                         int npairs, int wr_next, int wr_g,
                                         const float* __restrict__ usrc,
                                         __half* __restrict__ wdst, float* p) {
    int row = node * 32 + lane;
    float2 bb = ((const float2*)g_b)[row];
    float2 uu = ((const float2*)usrc)[row];
    float2 val = make_float2(bb.x + 0.5f * mix.x, bb.y + 0.5f * mix.y);
    ((float2*)g_F[slot])[row] = val;
    float2 gn = make_float2(val.x - uu.x, val.y - uu.y);
    if (wr_g) ((float2*)g_G[slot])[row] = gn;
    if (wr_next) {
        ((__half2*)wdst)[row] =
            __floats2half2_rn(2.f * fmaxf(val.x, 0.f) - val.x + bb.x,
                              2.f * fmaxf(val.y, 0.f) - val.y + bb.y);
    }
    for (int j = 0; j < npairs; ++j) {
        float2 gj = (j == slot) ? gn : ((const float2*)g_G[j])[row];
        p[j] = fmaf(gn.x, gj.x, fmaf(gn.y, gj.y, p[j]));
    }
}

// ---------------- fused SPMM + LDS.128 mix + G + Gram partials ----------------
__device__ void spmm_phase(int slot, int npairs, double* target, int wr_next, int wr_g,
                           const __half* __restrict__ wsrc,
                           const float* __restrict__ usrc,
                           __half* __restrict__ wdst,
                           SmemU* su, double (*red)[5]) {
    int warp = threadIdx.x >> 5, lane = threadIdx.x & 31;
    int w = blockIdx.x * WPB + warp;
    const int2*    __restrict__ eg = g_edge;
    const __half2* __restrict__ wv = (const __half2*)wsrc;
    float p[5];
#pragma unroll
    for (int j = 0; j < 5; j++) p[j] = 0.f;

    int n = g_wstart[w], ne = g_wstart[w + 1];

    for (; n + 1 < ne; n += 2) {
        // counts rounded up to multiple of 4 edges (padding zero-filled)
        int hcA = ((g_cur[n] + 3) & ~3) >> 1;
        int hcB = ((g_cur[n + 1] + 3) & ~3) >> 1;
        float2 accA, accB;
        gather2(eg, wv, n * PAD, hcA, (n + 1) * PAD, hcB, lane, accA, accB);

        __syncwarp();
        su->mix.s[warp][lane] = make_ulonglong2(pack2(accA), pack2(accB));
        __syncwarp();

        ull PA = 0ull, QA = 0ull, PB = 0ull, QB = 0ull;
#pragma unroll
        for (int m = 0; m < 32; ++m) {
            ulonglong2 sp = su->mix.s[warp][m];   // broadcast LDS.128
            ulonglong2 T  = su->mix.T[m][lane];   // conflict-free LDS.128
            fma2(PA, T.x, sp.x); fma2(QA, T.y, sp.x);
            fma2(PB, T.x, sp.y); fma2(QB, T.y, sp.y);
        }
        float2 pA = unpack2(PA), qA = unpack2(QA);
        float2 pB = unpack2(PB), qB = unpack2(QB);
        epilogue(n,     lane, make_float2(pA.x + pA.y, qA.x + qA.y),
                 slot, npairs, wr_next, wr_g, usrc, wdst, p);
        epilogue(n + 1, lane, make_float2(pB.x + pB.y, qB.x + qB.y),
                 slot, npairs, wr_next, wr_g, usrc, wdst, p);
    }
    if (n < ne) {
        int hcA = ((g_cur[n] + 3) & ~3) >> 1;
        float2 acc, dummy;
        gather2(eg, wv, n * PAD, hcA, n * PAD, 0, lane, acc, dummy);
        __syncwarp();
        su->mix.s[warp][lane] = make_ulonglong2(pack2(acc), 0ull);
        __syncwarp();
        ull PA = 0ull, QA = 0ull;
#pragma unroll
        for (int m = 0; m < 32; ++m) {
            ulonglong2 sp = su->mix.s[warp][m];
            ulonglong2 T  = su->mix.T[m][lane];
            fma2(PA, T.x, sp.x);
            fma2(QA, T.y, sp.x);
        }
        float2 pA = unpack2(PA), qA = unpack2(QA);
        epilogue(n, lane, make_float2(pA.x + pA.y, qA.x + qA.y),
                 slot, npairs, wr_next, wr_g, usrc, wdst, p);
    }

#pragma unroll
    for (int j = 0; j < 5; ++j)
        for (int off = 16; off > 0; off >>= 1)
            p[j] += __shfl_down_sync(0xffffffffu, p[j], off);
    __syncthreads();
    if (lane == 0)
        for (int j = 0; j < 5; ++j) red[warp][j] = (double)p[j];
    __syncthreads();
    if (threadIdx.x < npairs) {
        int j = threadIdx.x;
        double s = 0.0;
        for (int ww = 0; ww < WPB; ww++) s += red[ww][j];
        atomicAdd(&target[j], s);
    }
}

// ---------------- combine(k): Gram merge + 5x5 solve + u_new (+ fused decode at k=4) ----------------
__device__ void combine_phase(int k, float* sa, const float* __restrict__ decW,
                              float* __restrict__ out) {
    if (threadIdx.x == 0) {
        double M[5][5];
        const double* base = g_GGbuf[k & 1];
        int c = 0;
        for (int i = 0; i < 5; i++)
            for (int j = 0; j <= i; j++) { M[i][j] = base[c]; M[j][i] = base[c]; c++; }
        if (k > 0) {
            int idx = k - 1;
            const double* row = g_GGrow[(k - 1) & 1];
            for (int j = 0; j < 5; j++) { M[idx][j] = row[j]; M[j][idx] = row[j]; }
        }
        if (blockIdx.x == 0 && k < AAM - 1) {
            c = 0;
            for (int i = 0; i < 5; i++)
                for (int j = 0; j <= i; j++) g_GGbuf[(k + 1) & 1][c++] = M[i][j];
            for (int j = 0; j < 5; j++) g_GGrow[k & 1][j] = 0.0;
        }
        float A[5][6];
        for (int i = 0; i < 5; i++) {
            for (int j = 0; j < 5; j++) A[i][j] = (float)M[i][j];
            A[i][i] += 1e-4f;
            A[i][5] = 1.f;
        }
        for (int kk = 0; kk < 5; kk++) {
            int piv = kk; float mx = fabsf(A[kk][kk]);
            for (int r = kk + 1; r < 5; r++)
                if (fabsf(A[r][kk]) > mx) { mx = fabsf(A[r][kk]); piv = r; }
            if (piv != kk)
                for (int j = 0; j < 6; j++) { float t = A[kk][j]; A[kk][j] = A[piv][j]; A[piv][j] = t; }
            float inv = 1.f / A[kk][kk];
            for (int r = kk + 1; r < 5; r++) {
                float f = A[r][kk] * inv;
                for (int j = kk; j < 6; j++) A[r][j] -= f * A[kk][j];
            }
        }
        float a[5];
        for (int kk = 4; kk >= 0; kk--) {
            float s = A[kk][5];
            for (int j = kk + 1; j < 5; j++) s -= A[kk][j] * a[j];
            a[kk] = s / A[kk][kk];
        }
        float sum = a[0] + a[1] + a[2] + a[3] + a[4];
        for (int j = 0; j < 5; j++) sa[j] = a[j] / sum;
    }
    __syncthreads();
    float a0 = sa[0], a1 = sa[1], a2 = sa[2], a3 = sa[3], a4 = sa[4];

    int warp = threadIdx.x >> 5, lane = threadIdx.x & 31;
    int g = blockIdx.x * WPB + warp;
    const float2* F0 = (const float2*)g_F[0];
    const float2* F1 = (const float2*)g_F[1];
    const float2* F2 = (const float2*)g_F[2];
    const float2* F3 = (const float2*)g_F[3];
    const float2* F4 = (const float2*)g_F[4];
    for (int node = g; node < N_NODES; node += NWARPS) {
        int idx = node * 32 + lane;
        float2 f0 = F0[idx], f1 = F1[idx], f2 = F2[idx], f3 = F3[idx], f4 = F4[idx];
        float2 un;
        un.x = a0 * f0.x + a1 * f1.x + a2 * f2.x + a3 * f3.x + a4 * f4.x;
        un.y = a0 * f0.y + a1 * f1.y + a2 * f2.y + a3 * f3.y + a4 * f4.y;
        if (k < AAM - 1) {
            ((float2*)g_u)[idx] = un;
            float2 bb = ((const float2*)g_b)[idx];
            ((__half2*)g_wbuf[0])[idx] =
                __floats2half2_rn(2.f * fmaxf(un.x, 0.f) - un.x + bb.x,
                                  2.f * fmaxf(un.y, 0.f) - un.y + bb.y);
        } else {
            float rx = fmaxf(un.x, 0.f), ry = fmaxf(un.y, 0.f);
            int o = lane & 15, half = lane >> 4;
            float acc = 0.f;
#pragma unroll
            for (int i = 0; i < 16; i++) {
                int m = half * 16 + i;
                float sx = __shfl_sync(0xffffffffu, rx, m);
                float sy = __shfl_sync(0xffffffffu, ry, m);
                acc = fmaf(sx, decW[(2 * m) * 16 + o], acc);
                acc = fmaf(sy, decW[(2 * m + 1) * 16 + o], acc);
            }
            acc += __shfl_down_sync(0xffffffffu, acc, 16);
            if (half == 0) out[node * 16 + o] = acc;
        }
    }
}

// ---------------- the single persistent kernel ----------------
__global__ void __launch_bounds__(TPB, BLK_PER_SM) k_mega(
    const float* __restrict__ x, const int* __restrict__ ei,
    const float* __restrict__ ew, const float* __restrict__ encW,
    const float* __restrict__ encb, const float* __restrict__ cayB,
    const float* __restrict__ decW, float* __restrict__ out)
{
    __shared__ SmemU su;
    __shared__ double red[WPB][5];
    __shared__ float sa[5];

    const int* src = ei;
    const int* dst = ei + N_EDGES;
    int gtid = blockIdx.x * TPB + threadIdx.x;

    // Phase 1: one-pass padded-row scatter (g_cur pre-zeroed) || encoder || zero GGbuf[0]
    for (int e = gtid; e < N_EDGES; e += NTHREADS) {
        int d = dst[e];
        int pos = atomicAdd(&g_cur[d], 1);
        g_edge[d * PAD + pos] = make_int2(src[e], __float_as_int(ew[e]));
    }
    if (gtid < 15) g_GGbuf[0][gtid] = 0.0;
    encode_phase(x, encW, encb, &su);
    gbar();

    // Phase 2: count-prefix scan (block 0) || Cayley theta (block 1)
    //          || zero-fill row padding to multiple of 4 edges (blocks >= 2)
    if (blockIdx.x == 0) {
        int t = threadIdx.x;
        const int CH = (N_NODES + TPB - 1) / TPB;   // 20
        int beg = t * CH, end = beg + CH; if (end > N_NODES) end = N_NODES;
        int s = 0;
        for (int i = beg; i < end; i++) s += g_cur[i];
        su.part[t] = s;
        __syncthreads();
        for (int d = 1; d < TPB; d <<= 1) {
            int v = (t >= d) ? su.part[t - d] : 0;
            __syncthreads();
            su.part[t] += v;
            __syncthreads();
        }
        int off = (t > 0) ? su.part[t - 1] : 0;
        for (int i = beg; i < end; i++) {
            g_rowptr[i] = off;
            off += g_cur[i];
        }
        if (t == 0) g_rowptr[N_NODES] = N_EDGES;
    } else if (blockIdx.x == 1) {
        theta_phase(cayB, &su);
    } else {
        int base = (blockIdx.x - 2) * TPB + threadIdx.x;
        for (int i = base; i < N_NODES; i += (GRID_BLOCKS - 2) * TPB) {
            int c = g_cur[i];
            int cr = (c + 3) & ~3;
            for (int e = c; e < cr; e++)
                g_edge[i * PAD + e] = make_int2(0, 0);   // w = 0.0f
        }
    }
    gbar();

    // Phase 3: balanced warp partition || stage packed Theta
    if (gtid <= NWARPS) {
        if (gtid == NWARPS) {
            g_wstart[NWARPS] = N_NODES;
        } else {
            long long target = (long long)gtid * COST_TOTAL / NWARPS;
            int lo = 0, hi = N_NODES;
            while (lo < hi) {
                int mid = (lo + hi) >> 1;
                long long c = (long long)g_rowptr[mid] + (long long)NODE_COST * mid;
                if (c < target) lo = mid + 1; else hi = mid;
            }
            g_wstart[gtid] = lo;
        }
    }
    for (int i = threadIdx.x; i < 1024; i += TPB) {
        int m = i >> 5, l = i & 31;
        float a0 = g_ThT[(2 * m) * 64 + 2 * l];
        float a1 = g_ThT[(2 * m + 1) * 64 + 2 * l];
        float b0 = g_ThT[(2 * m) * 64 + 2 * l + 1];
        float b1 = g_ThT[(2 * m + 1) * 64 + 2 * l + 1];
        su.mix.T[m][l] = make_ulonglong2(pack2(make_float2(a0, a1)),
                                         pack2(make_float2(b0, b1)));
    }
    gbar();

    // history: 5 PR sweeps (w ping-pong); uu read from b / F[i-1]
    for (int i = 0; i < AAM; i++) {
        spmm_phase(i, i + 1, &g_GGbuf[0][i * (i + 1) / 2], (i < AAM - 1) ? 1 : 0, 1,
                   g_wbuf[i & 1], (i == 0) ? g_b : g_F[i - 1], g_wbuf[(i + 1) & 1],
                   &su, red);
        gbar();
    }

    // Anderson: combine -> spmm (last g() dead); final combine fuses decode.
    for (int k = 0; k < AAM; k++) {
        combine_phase(k, sa, decW, out);
        if (k < AAM - 1) {
            gbar();
            spmm_phase(k, 5, g_GGrow[k & 1], 0, (k < AAM - 2) ? 1 : 0,
                       g_wbuf[0], g_u, 0, &su, red);
            gbar();
        }
    }

    // tail: re-zero g_cur for the NEXT launch (last reader was spmm(k=3), behind a gbar)
    for (int i = gtid; i < N_NODES; i += NTHREADS) g_cur[i] = 0;
}

// ---------------- launch: ONE kernel ----------------
extern "C" void kernel_launch(void* const* d_in, const int* in_sizes, int n_in,
                              void* d_out, int out_size) {
    const float* x    = (const float*)d_in[0];
    const int*   ei   = (const int*)  d_in[1];
    const float* ew   = (const float*)d_in[2];
    const float* encW = (const float*)d_in[3];
    const float* encb = (const float*)d_in[4];
    const float* cayB = (const float*)d_in[5];
    const float* decW = (const float*)d_in[6];
    float* out = (float*)d_out;

    k_mega<<<GRID_BLOCKS, TPB>>>(x, ei, ew, encW, encb, cayB, decW, out);
}